// round 4
// baseline (speedup 1.0000x reference)
#include <cuda_runtime.h>
#include <math.h>
#include <stdint.h>

#define D    768
#define F    3072
#define SEQ  2048
#define BAT  2
#define NH   12
#define HD   64
#define NROW  (BAT*SEQ)   // 4096
#define NHEAD (BAT*NH)    // 24

// ---------------- scratch (device globals; allocations forbidden) -----------
__device__ float g_h1 [NROW*D];
__device__ float g_qkv[(size_t)NROW*3*D];
__device__ float g_wqkvT[3*D*D];
__device__ float g_bqkv[3*D];
__device__ float g_woT[D*D];
__device__ float g_w1T[D*F];
__device__ float g_w2T[D*F];
__device__ float g_vT [(size_t)NHEAD*HD*SEQ];
__device__ float g_e  [(size_t)NHEAD*SEQ*SEQ];   // 402 MB
__device__ float g_partial[(size_t)NHEAD*SEQ*16];
__device__ float g_invsum [(size_t)NHEAD*SEQ];
__device__ float g_ctx[NROW*D];
__device__ float g_x2 [NROW*D];
__device__ float g_h2 [NROW*D];
__device__ float g_mlp[(size_t)NROW*F];

// ---------------- helpers ----------------------------------------------------
__device__ __forceinline__ uint32_t smem_u32(const void* p) {
    uint32_t a;
    asm("{ .reg .u64 t; cvta.to.shared.u64 t, %1; cvt.u32.u64 %0, t; }" : "=r"(a) : "l"(p));
    return a;
}
__device__ __forceinline__ float rna_tf32(float x) {
    float r;
    asm("cvt.rna.tf32.f32 %0, %1;" : "=f"(r) : "f"(x));
    return r;
}
__device__ __forceinline__ void mma8(float* d, const uint32_t* a, const uint32_t* b) {
    asm volatile(
        "mma.sync.aligned.m16n8k8.row.col.f32.tf32.tf32.f32 "
        "{%0,%1,%2,%3}, {%4,%5,%6,%7}, {%8,%9}, {%0,%1,%2,%3};"
        : "+f"(d[0]), "+f"(d[1]), "+f"(d[2]), "+f"(d[3])
        : "r"(a[0]), "r"(a[1]), "r"(a[2]), "r"(a[3]), "r"(b[0]), "r"(b[1]));
}
#define CP16(dst, src) asm volatile("cp.async.cg.shared.global [%0], [%1], 16;" :: "r"(dst), "l"(src) : "memory")
#define CP_COMMIT()    asm volatile("cp.async.commit_group;" ::: "memory")
#define CP_WAIT2()     asm volatile("cp.async.wait_group 2;" ::: "memory")

// ---------------- tf32 mma.sync GEMM -----------------------------------------
// C[M,N] = scale*(A[M,K] @ Bt[N,K]^T) (+bias) (GELU?) (round?) (+res)
// A, Bt K-major. CTA tile 128 x BN, 4 warps (2x2), warp tile 64 x BN/2, BK=32.
// EXPSUM: also emit per-row partial sums of exp(C) into `partial`
// (layout [z*SEQ + row][16], one slot per blockIdx.x).
template<int BN, bool GELU, bool ROUND, bool EXPSUM>
__global__ void __launch_bounds__(128, 2) mm_tf32(
    const float* __restrict__ A, int lda, size_t sA1, size_t sA0,
    const float* __restrict__ Bt, int ldb, size_t sB1, size_t sB0,
    float* __restrict__ C, int ldc, size_t sC1, size_t sC0,
    const float* __restrict__ bias, const float* __restrict__ res, int ldr,
    int K, int zmod, float scale, float* __restrict__ partial)
{
    constexpr int S = 3;
    constexpr int WN = BN / 2;
    constexpr int NF = WN / 8;          // n-frags per warp
    constexpr int AF = 128 * 32;        // A floats per stage
    constexpr int BF = BN * 32;         // B floats per stage
    constexpr int STG = AF + BF;

    extern __shared__ float sm[];
    const uint32_t sb = smem_u32(sm);

    int tid = threadIdx.x, w = tid >> 5, lane = tid & 31;
    int wm = w >> 1, wn = w & 1;
    int q = lane >> 2, c4 = lane & 3;

    int z = blockIdx.z, z1 = z / zmod, z0 = z - z1 * zmod;
    A  += z1 * sA1 + z0 * sA0;
    Bt += z1 * sB1 + z0 * sB0;
    C  += z1 * sC1 + z0 * sC0;
    int row0 = blockIdx.y * 128, col0 = blockIdx.x * BN;

    const int nch = K >> 5;

    auto load_chunk = [&](int ch, int st) {
        const float* Ak = A + (size_t)row0 * lda + ch * 32;
        const float* Bk = Bt + (size_t)col0 * ldb + ch * 32;
        uint32_t base = sb + st * STG * 4;
        #pragma unroll 4
        for (int idx = tid; idx < (128 + BN) * 8; idx += 128) {
            int h = idx & 7, kb = h >> 1, half = h & 1;
            if (idx < 1024) {
                int m = idx >> 3;
                uint32_t fo = kb * 1024 + ((m * 8 + half * 4) ^ (m & 4));
                CP16(base + fo * 4, Ak + (size_t)m * lda + h * 4);
            } else {
                int n = (idx >> 3) - 128;
                uint32_t fo = AF + kb * (BN * 8) + ((n * 8 + half * 4) ^ (n & 4));
                CP16(base + fo * 4, Bk + (size_t)n * ldb + h * 4);
            }
        }
    };

    for (int cc = 0; cc < S; cc++) {
        if (cc < nch) load_chunk(cc, cc);
        CP_COMMIT();
    }

    float acc[4][NF][4];
    #pragma unroll
    for (int i = 0; i < 4; i++)
        #pragma unroll
        for (int j = 0; j < NF; j++)
            #pragma unroll
            for (int t = 0; t < 4; t++) acc[i][j][t] = 0.0f;

    const uint32_t* smu = (const uint32_t*)sm;

    for (int i = 0; i < nch; i++) {
        int st = i % S;
        CP_WAIT2();
        __syncthreads();
        const uint32_t* Au = smu + st * STG;
        const uint32_t* Bu = Au + AF;
        #pragma unroll
        for (int kb = 0; kb < 4; kb++) {
            uint32_t a[4][4], b[NF][2];
            #pragma unroll
            for (int mf = 0; mf < 4; mf++) {
                int r = wm * 64 + mf * 16 + q;
                a[mf][0] = Au[kb * 1024 + ((r * 8 + c4) ^ (r & 4))];
                a[mf][1] = Au[kb * 1024 + (((r + 8) * 8 + c4) ^ ((r + 8) & 4))];
                a[mf][2] = Au[kb * 1024 + ((r * 8 + c4 + 4) ^ (r & 4))];
                a[mf][3] = Au[kb * 1024 + (((r + 8) * 8 + c4 + 4) ^ ((r + 8) & 4))];
            }
            #pragma unroll
            for (int nf = 0; nf < NF; nf++) {
                int n = wn * WN + nf * 8 + q;
                b[nf][0] = Bu[kb * (BN * 8) + ((n * 8 + c4) ^ (n & 4))];
                b[nf][1] = Bu[kb * (BN * 8) + ((n * 8 + c4 + 4) ^ (n & 4))];
            }
            #pragma unroll
            for (int mf = 0; mf < 4; mf++)
                #pragma unroll
                for (int nf = 0; nf < NF; nf++)
                    mma8(acc[mf][nf], a[mf], b[nf]);
        }
        __syncthreads();
        int nx = i + S;
        if (nx < nch) load_chunk(nx, st);
        CP_COMMIT();
    }

    // epilogue
    float* rpart = sm;   // [2][128], reused after main loop
    #pragma unroll
    for (int mf = 0; mf < 4; mf++) {
        #pragma unroll
        for (int half = 0; half < 2; half++) {
            int m = row0 + wm * 64 + mf * 16 + q + half * 8;
            float* crow = C + (size_t)m * ldc;
            const float* rrow = res ? res + (size_t)m * ldr : nullptr;
            float rs = 0.0f;
            #pragma unroll
            for (int nf = 0; nf < NF; nf++) {
                int n = col0 + wn * WN + nf * 8 + c4 * 2;
                float v0 = acc[mf][nf][half * 2 + 0] * scale;
                float v1 = acc[mf][nf][half * 2 + 1] * scale;
                if (bias) { v0 += bias[n]; v1 += bias[n + 1]; }
                if (GELU) {
                    v0 = 0.5f * v0 * (1.0f + erff(v0 * 0.70710678118654752f));
                    v1 = 0.5f * v1 * (1.0f + erff(v1 * 0.70710678118654752f));
                }
                if (ROUND) { v0 = rna_tf32(v0); v1 = rna_tf32(v1); }
                if (EXPSUM) rs += __expf(v0) + __expf(v1);
                if (res) { v0 += rrow[n]; v1 += rrow[n + 1]; }
                *(float2*)(crow + n) = make_float2(v0, v1);
            }
            if (EXPSUM) {
                rs += __shfl_xor_sync(0xffffffffu, rs, 1);
                rs += __shfl_xor_sync(0xffffffffu, rs, 2);
                if (c4 == 0)
                    rpart[wn * 128 + wm * 64 + mf * 16 + half * 8 + q] = rs;
            }
        }
    }
    if (EXPSUM) {
        __syncthreads();
        float s = rpart[tid] + rpart[128 + tid];
        partial[((size_t)blockIdx.z * SEQ + row0 + tid) * 16 + blockIdx.x] = s;
    }
}

// ---------------- rowsum -> inverse ------------------------------------------
__global__ void rowsum_inv_kernel(const float* __restrict__ p, float* __restrict__ inv)
{
    int i = blockIdx.x * 256 + threadIdx.x;   // 0 .. NHEAD*SEQ-1
    const float4* r = (const float4*)(p + (size_t)i * 16);
    float4 a = r[0], b = r[1], c = r[2], d = r[3];
    float s = a.x + a.y + a.z + a.w + b.x + b.y + b.z + b.w
            + c.x + c.y + c.z + c.w + d.x + d.y + d.z + d.w;
    inv[i] = 1.0f / s;
}

// ---------------- fused attention tail: attn = exp(E)*inv ; ctx = E @ v ------
// grid (SEQ/128, NHEAD). A = E (K-major rows of 2048), Bt = vT[z] (64 x 2048).
__global__ void __launch_bounds__(128, 2) attn_ctx_kernel(
    const float* __restrict__ E, const float* __restrict__ vT,
    const float* __restrict__ invsum,
    float* __restrict__ attn, float* __restrict__ ctx)
{
    constexpr int S = 3, BN = 64, WN = 32, NF = 4;
    constexpr int AF = 128 * 32, BF = BN * 32, STG = AF + BF;

    extern __shared__ float sm[];
    const uint32_t sb = smem_u32(sm);

    int tid = threadIdx.x, w = tid >> 5, lane = tid & 31;
    int wm = w >> 1, wn = w & 1;
    int q = lane >> 2, c4 = lane & 3;

    int z = blockIdx.y, b = z / NH, h = z - b * NH;
    int row0 = blockIdx.x * 128;

    const float* A  = E  + (size_t)z * SEQ * SEQ;
    const float* Bt = vT + (size_t)z * HD * SEQ;
    float inv = invsum[z * SEQ + row0 + tid];
    float* attnRow = attn + (size_t)z * SEQ * SEQ + (size_t)(row0 + tid) * SEQ;

    const int nch = SEQ >> 5;   // 64

    auto load_chunk = [&](int ch, int st) {
        const float* Ak = A + (size_t)row0 * SEQ + ch * 32;
        const float* Bk = Bt + (size_t)ch * 32;
        uint32_t base = sb + st * STG * 4;
        #pragma unroll 4
        for (int idx = tid; idx < (128 + BN) * 8; idx += 128) {
            int hh = idx & 7, kb = hh >> 1, half = hh & 1;
            if (idx < 1024) {
                int m = idx >> 3;
                uint32_t fo = kb * 1024 + ((m * 8 + half * 4) ^ (m & 4));
                CP16(base + fo * 4, Ak + (size_t)m * SEQ + hh * 4);
            } else {
                int n = (idx >> 3) - 128;
                uint32_t fo = AF + kb * (BN * 8) + ((n * 8 + half * 4) ^ (n & 4));
                CP16(base + fo * 4, Bk + (size_t)n * SEQ + hh * 4);
            }
        }
    };

    for (int cc = 0; cc < S; cc++) {
        if (cc < nch) load_chunk(cc, cc);
        CP_COMMIT();
    }

    float acc[4][NF][4];
    #pragma unroll
    for (int i = 0; i < 4; i++)
        #pragma unroll
        for (int j = 0; j < NF; j++)
            #pragma unroll
            for (int t = 0; t < 4; t++) acc[i][j][t] = 0.0f;

    const uint32_t* smu = (const uint32_t*)sm;

    for (int i = 0; i < nch; i++) {
        int st = i % S;
        CP_WAIT2();
        __syncthreads();

        // --- attention output: thread tid owns row tid of this 128x32 A tile
        {
            const float4* As4 = (const float4*)(sm + st * STG);
            float* arow = attnRow + i * 32;
            #pragma unroll
            for (int kb = 0; kb < 4; kb++) {
                int fo = (kb * 1024 + tid * 8) >> 2;
                float4 lo = As4[fo], hi = As4[fo + 1];
                if (tid & 4) { float4 t = lo; lo = hi; hi = t; }
                float4 o0 = make_float4(__expf(lo.x) * inv, __expf(lo.y) * inv,
                                        __expf(lo.z) * inv, __expf(lo.w) * inv);
                float4 o1 = make_float4(__expf(hi.x) * inv, __expf(hi.y) * inv,
                                        __expf(hi.z) * inv, __expf(hi.w) * inv);
                *(float4*)(arow + kb * 8)     = o0;
                *(float4*)(arow + kb * 8 + 4) = o1;
            }
        }

        const uint32_t* Au = smu + st * STG;
        const uint32_t* Bu = Au + AF;
        #pragma unroll
        for (int kb = 0; kb < 4; kb++) {
            uint32_t a[4][4], bfr[NF][2];
            #pragma unroll
            for (int mf = 0; mf < 4; mf++) {
                int r = wm * 64 + mf * 16 + q;
                a[mf][0] = Au[kb * 1024 + ((r * 8 + c4) ^ (r & 4))];
                a[mf][1] = Au[kb * 1024 + (((r + 8) * 8 + c4) ^ ((r + 8) & 4))];
                a[mf][2] = Au[kb * 1024 + ((r * 8 + c4 + 4) ^ (r & 4))];
                a[mf][3] = Au[kb * 1024 + (((r + 8) * 8 + c4 + 4) ^ ((r + 8) & 4))];
            }
            #pragma unroll
            for (int nf = 0; nf < NF; nf++) {
                int n = wn * WN + nf * 8 + q;
                bfr[nf][0] = Bu[kb * (BN * 8) + ((n * 8 + c4) ^ (n & 4))];
                bfr[nf][1] = Bu[kb * (BN * 8) + ((n * 8 + c4 + 4) ^ (n & 4))];
            }
            #pragma unroll
            for (int mf = 0; mf < 4; mf++)
                #pragma unroll
                for (int nf = 0; nf < NF; nf++)
                    mma8(acc[mf][nf], a[mf], bfr[nf]);
        }
        __syncthreads();
        int nx = i + S;
        if (nx < nch) load_chunk(nx, st);
        CP_COMMIT();
    }

    // ctx epilogue (rounded: feeds Wo GEMM)
    #pragma unroll
    for (int mf = 0; mf < 4; mf++) {
        #pragma unroll
        for (int half = 0; half < 2; half++) {
            int m = row0 + wm * 64 + mf * 16 + q + half * 8;
            float* crow = ctx + ((size_t)b * SEQ + m) * D + h * HD;
            #pragma unroll
            for (int nf = 0; nf < NF; nf++) {
                int n = wn * WN + nf * 8 + c4 * 2;
                float v0 = rna_tf32(acc[mf][nf][half * 2 + 0]);
                float v1 = rna_tf32(acc[mf][nf][half * 2 + 1]);
                *(float2*)(crow + n) = make_float2(v0, v1);
            }
        }
    }
}

// ---------------- LayerNorm (rounds output to tf32) --------------------------
template<bool ROUND>
__global__ void ln_kernel(const float* __restrict__ x, const float* __restrict__ g,
                          const float* __restrict__ be, float* __restrict__ out)
{
    __shared__ float sh[16];
    int row = blockIdx.x, t = threadIdx.x;
    const float* xr = x + (size_t)row * D;
    float v0 = xr[t], v1 = xr[t + 256], v2 = xr[t + 512];
    float s = v0 + v1 + v2, sq = v0*v0 + v1*v1 + v2*v2;
    #pragma unroll
    for (int o = 16; o; o >>= 1) {
        s  += __shfl_down_sync(0xffffffffu, s,  o);
        sq += __shfl_down_sync(0xffffffffu, sq, o);
    }
    int lane = t & 31, w = t >> 5;
    if (lane == 0) { sh[w] = s; sh[8 + w] = sq; }
    __syncthreads();
    if (t < 8) {
        s = sh[t]; sq = sh[8 + t];
        #pragma unroll
        for (int o = 4; o; o >>= 1) {
            s  += __shfl_down_sync(0xffu, s,  o);
            sq += __shfl_down_sync(0xffu, sq, o);
        }
        if (t == 0) {
            float mu = s * (1.0f / 768.0f);
            float var = sq * (1.0f / 768.0f) - mu * mu;
            sh[0] = mu; sh[1] = rsqrtf(var + 1e-5f);
        }
    }
    __syncthreads();
    float mu = sh[0], r = sh[1];
    float* orow = out + (size_t)row * D;
    float o0 = (v0 - mu) * r * g[t]       + be[t];
    float o1 = (v1 - mu) * r * g[t + 256] + be[t + 256];
    float o2 = (v2 - mu) * r * g[t + 512] + be[t + 512];
    if (ROUND) { o0 = rna_tf32(o0); o1 = rna_tf32(o1); o2 = rna_tf32(o2); }
    orow[t] = o0; orow[t + 256] = o1; orow[t + 512] = o2;
}

// ---------------- weight transpose + round -----------------------------------
__global__ void transpose_round(const float* __restrict__ in, float* __restrict__ out,
                                int K, int N)
{
    __shared__ float tile[32][33];
    int k0 = blockIdx.y * 32, n0 = blockIdx.x * 32;
    int tx = threadIdx.x, ty = threadIdx.y;
    #pragma unroll
    for (int i = ty; i < 32; i += 8)
        tile[i][tx] = in[(size_t)(k0 + i) * N + n0 + tx];
    __syncthreads();
    #pragma unroll
    for (int i = ty; i < 32; i += 8)
        out[(size_t)(n0 + i) * K + k0 + tx] = rna_tf32(tile[tx][i]);
}

// per-head v transpose: vT[z][n][k] = qkv[(b*SEQ+k)*2304 + 1536 + h*64 + n]
__global__ void vtrans_kernel(const float* __restrict__ qkv, float* __restrict__ vT)
{
    __shared__ float tile[32][33];
    int z = blockIdx.z, b = z / NH, h = z - b * NH;
    int k0 = blockIdx.x * 32, n0 = blockIdx.y * 32;
    int tx = threadIdx.x, ty = threadIdx.y;
    const float* src = qkv + (size_t)b * SEQ * (3 * D) + 2 * D + h * HD;
    #pragma unroll
    for (int i = ty; i < 32; i += 8)
        tile[i][tx] = src[(size_t)(k0 + i) * (3 * D) + n0 + tx];
    __syncthreads();
    float* dst = vT + (size_t)z * HD * SEQ;
    #pragma unroll
    for (int i = ty; i < 32; i += 8)
        dst[(size_t)(n0 + i) * SEQ + k0 + tx] = tile[tx][i];
}

__global__ void pack_bias(const float* bq, const float* bk, const float* bv, float* o)
{
    int j = blockIdx.x * 256 + threadIdx.x;
    if (j < 3 * D) o[j] = (j < D) ? bq[j] : (j < 2 * D) ? bk[j - D] : bv[j - 2 * D];
}

// ---------------- launch ------------------------------------------------------
extern "C" void kernel_launch(void* const* d_in, const int* in_sizes, int n_in,
                              void* d_out, int out_size)
{
    const float* x   = (const float*)d_in[0];
    const float* wq  = (const float*)d_in[1];  const float* bq  = (const float*)d_in[2];
    const float* wk  = (const float*)d_in[3];  const float* bk  = (const float*)d_in[4];
    const float* wv  = (const float*)d_in[5];  const float* bv  = (const float*)d_in[6];
    const float* wo  = (const float*)d_in[7];  const float* bo  = (const float*)d_in[8];
    const float* w1  = (const float*)d_in[9];  const float* b1  = (const float*)d_in[10];
    const float* w2  = (const float*)d_in[11]; const float* b2  = (const float*)d_in[12];
    const float* g1  = (const float*)d_in[13]; const float* be1 = (const float*)d_in[14];
    const float* g2  = (const float*)d_in[15]; const float* be2 = (const float*)d_in[16];

    float* out      = (float*)d_out;
    float* attn_out = out + (size_t)NROW * D;

    float *h1, *qkv, *wqkvT, *bqkv, *woT, *w1T, *w2T, *vT, *e, *part, *invs, *ctx, *x2, *h2, *mlp;
    cudaGetSymbolAddress((void**)&h1,    g_h1);
    cudaGetSymbolAddress((void**)&qkv,   g_qkv);
    cudaGetSymbolAddress((void**)&wqkvT, g_wqkvT);
    cudaGetSymbolAddress((void**)&bqkv,  g_bqkv);
    cudaGetSymbolAddress((void**)&woT,   g_woT);
    cudaGetSymbolAddress((void**)&w1T,   g_w1T);
    cudaGetSymbolAddress((void**)&w2T,   g_w2T);
    cudaGetSymbolAddress((void**)&vT,    g_vT);
    cudaGetSymbolAddress((void**)&e,     g_e);
    cudaGetSymbolAddress((void**)&part,  g_partial);
    cudaGetSymbolAddress((void**)&invs,  g_invsum);
    cudaGetSymbolAddress((void**)&ctx,   g_ctx);
    cudaGetSymbolAddress((void**)&x2,    g_x2);
    cudaGetSymbolAddress((void**)&h2,    g_h2);
    cudaGetSymbolAddress((void**)&mlp,   g_mlp);

    const int SM128 = 3 * (128 * 32 + 128 * 32) * 4;   // 96 KB
    const int SM64  = 3 * (128 * 32 + 64 * 32) * 4;    // 72 KB
    cudaFuncSetAttribute(mm_tf32<128, false, true,  false>, cudaFuncAttributeMaxDynamicSharedMemorySize, SM128);
    cudaFuncSetAttribute(mm_tf32<128, false, true,  true >, cudaFuncAttributeMaxDynamicSharedMemorySize, SM128);
    cudaFuncSetAttribute(mm_tf32<128, false, false, false>, cudaFuncAttributeMaxDynamicSharedMemorySize, SM128);
    cudaFuncSetAttribute(mm_tf32<128, true,  true,  false>, cudaFuncAttributeMaxDynamicSharedMemorySize, SM128);
    cudaFuncSetAttribute(attn_ctx_kernel, cudaFuncAttributeMaxDynamicSharedMemorySize, SM64);

    dim3 tb(32, 8);
    // launches 0-4: QKV prerequisites (so launch #5 = QKV GEMM for ncu -s 5)
    transpose_round<<<dim3(D / 32, D / 32), tb>>>(wq, wqkvT,             D, D);
    transpose_round<<<dim3(D / 32, D / 32), tb>>>(wk, wqkvT + D * D,     D, D);
    transpose_round<<<dim3(D / 32, D / 32), tb>>>(wv, wqkvT + 2 * D * D, D, D);
    pack_bias<<<(3 * D + 255) / 256, 256>>>(bq, bk, bv, bqkv);
    ln_kernel<true><<<NROW, 256>>>(x, g1, be1, h1);

    // 5. fused QKV: qkv[4096,2304] = h1 @ [wq|wk|wv] + bias  (rounded)
    mm_tf32<128, false, true, false><<<dim3(3 * D / 128, NROW / 128, 1), 128, SM128>>>(
        h1, D, 0, 0, wqkvT, D, 0, 0, qkv, 3 * D, 0, 0, bqkv, nullptr, 0, D, 1, 1.0f, nullptr);

    // 6. per-head v transpose -> vT[24][64][2048]
    vtrans_kernel<<<dim3(SEQ / 32, HD / 32, NHEAD), tb>>>(qkv, vT);

    // 7. energy = q k^T / 8  (rounded) + per-row exp partials
    mm_tf32<128, false, true, true><<<dim3(SEQ / 128, SEQ / 128, NHEAD), 128, SM128>>>(
        qkv,     3 * D, (size_t)SEQ * 3 * D, HD,
        qkv + D, 3 * D, (size_t)SEQ * 3 * D, HD,
        e, SEQ, (size_t)NH * SEQ * SEQ, (size_t)SEQ * SEQ,
        nullptr, nullptr, 0, HD, NH, 0.125f, part);

    // 8. rowsum -> inverse
    rowsum_inv_kernel<<<NHEAD * SEQ / 256, 256>>>(part, invs);

    // 9. fused: attention = exp(E)*inv ; ctx = E @ v
    attn_ctx_kernel<<<dim3(SEQ / 128, NHEAD), 128, SM64>>>(e, vT, invs, attn_out, ctx);

    // 10-11. x2 = x + ctx @ wo + bo
    transpose_round<<<dim3(D / 32, D / 32), tb>>>(wo, woT, D, D);
    mm_tf32<128, false, false, false><<<dim3(D / 128, NROW / 128, 1), 128, SM128>>>(
        ctx, D, 0, 0, woT, D, 0, 0, x2, D, 0, 0, bo, x, D, D, 1, 1.0f, nullptr);

    // 12. LN2 (rounded)
    ln_kernel<true><<<NROW, 256>>>(x2, g2, be2, h2);

    // 13-14. mlp = gelu(h2 @ w1 + b1)  (rounded)
    transpose_round<<<dim3(F / 32, D / 32), tb>>>(w1, w1T, D, F);
    mm_tf32<128, true, true, false><<<dim3(F / 128, NROW / 128, 1), 128, SM128>>>(
        h2, D, 0, 0, w1T, D, 0, 0, mlp, F, 0, 0, b1, nullptr, 0, D, 1, 1.0f, nullptr);

    // 15-16. out = x2 + mlp @ w2 + b2
    transpose_round<<<dim3(D / 32, F / 32), tb>>>(w2, w2T, F, D);
    mm_tf32<128, false, false, false><<<dim3(D / 128, NROW / 128, 1), 128, SM128>>>(
        mlp, F, 0, 0, w2T, F, 0, 0, out, D, 0, 0, b2, x2, D, F, 1, 1.0f, nullptr);
}

// round 5
// speedup vs baseline: 1.1126x; 1.1126x over previous
#include <cuda_runtime.h>
#include <math.h>
#include <stdint.h>

#define D    768
#define F    3072
#define SEQ  2048
#define BAT  2
#define NH   12
#define HD   64
#define NROW  (BAT*SEQ)   // 4096
#define NHEAD (BAT*NH)    // 24

// ---------------- scratch (device globals; allocations forbidden) -----------
__device__ float g_h1 [NROW*D];
__device__ float g_qkv[(size_t)NROW*3*D];
__device__ float g_wqkvT[3*D*D];
__device__ float g_bqkv[3*D];
__device__ float g_woT[D*D];
__device__ float g_w1T[D*F];
__device__ float g_w2T[D*F];
__device__ float g_vT [(size_t)NHEAD*HD*SEQ];
__device__ float g_e  [(size_t)NHEAD*SEQ*SEQ];   // 402 MB
__device__ float g_ctx[NROW*D];
__device__ float g_x2 [NROW*D];
__device__ float g_h2 [NROW*D];
__device__ float g_mlp[(size_t)NROW*F];

// ---------------- helpers ----------------------------------------------------
__device__ __forceinline__ uint32_t smem_u32(const void* p) {
    uint32_t a;
    asm("{ .reg .u64 t; cvta.to.shared.u64 t, %1; cvt.u32.u64 %0, t; }" : "=r"(a) : "l"(p));
    return a;
}
__device__ __forceinline__ float rna_tf32(float x) {
    float r;
    asm("cvt.rna.tf32.f32 %0, %1;" : "=f"(r) : "f"(x));
    return r;
}
__device__ __forceinline__ void mma8(float* d, const uint32_t* a, const uint32_t* b) {
    asm volatile(
        "mma.sync.aligned.m16n8k8.row.col.f32.tf32.tf32.f32 "
        "{%0,%1,%2,%3}, {%4,%5,%6,%7}, {%8,%9}, {%0,%1,%2,%3};"
        : "+f"(d[0]), "+f"(d[1]), "+f"(d[2]), "+f"(d[3])
        : "r"(a[0]), "r"(a[1]), "r"(a[2]), "r"(a[3]), "r"(b[0]), "r"(b[1]));
}
#define CP16(dst, src) asm volatile("cp.async.cg.shared.global [%0], [%1], 16;" :: "r"(dst), "l"(src) : "memory")
#define CP_COMMIT()    asm volatile("cp.async.commit_group;" ::: "memory")
#define CP_WAIT2()     asm volatile("cp.async.wait_group 2;" ::: "memory")

// ---------------- tf32 mma.sync GEMM -----------------------------------------
// C[M,N] = scale*(A[M,K] @ Bt[N,K]^T) (+bias) (GELU?) (round?) (+res)
// A, Bt K-major. CTA tile 128 x BN, 256 threads (8 warps), BK=32, 3 stages.
// BN=128: warps 2x4 (warp tile 64x32). BN=64: warps 4x2 (warp tile 32x32).
template<int BN, bool GELU, bool ROUND>
__global__ void __launch_bounds__(256, 2) mm_tf32(
    const float* __restrict__ A, int lda, size_t sA1, size_t sA0,
    const float* __restrict__ Bt, int ldb, size_t sB1, size_t sB0,
    float* __restrict__ C, int ldc, size_t sC1, size_t sC0,
    const float* __restrict__ bias, const float* __restrict__ res, int ldr,
    int K, int zmod, float scale)
{
    constexpr int S   = 3;
    constexpr int WMW = (BN == 128) ? 2 : 4;      // warps along M
    constexpr int WNW = 8 / WMW;                  // warps along N
    constexpr int MF  = 128 / WMW / 16;           // m-frags per warp
    constexpr int NF  = BN / WNW / 8;             // n-frags per warp
    constexpr int AF  = 128 * 32;                 // A floats per stage
    constexpr int BF  = BN * 32;
    constexpr int STG = AF + BF;

    extern __shared__ float sm[];
    const uint32_t sb = smem_u32(sm);

    int tid = threadIdx.x, w = tid >> 5, lane = tid & 31;
    int wm = w / WNW, wn = w % WNW;
    int q = lane >> 2, c4 = lane & 3;

    int z = blockIdx.z, z1 = z / zmod, z0 = z - z1 * zmod;
    A  += z1 * sA1 + z0 * sA0;
    Bt += z1 * sB1 + z0 * sB0;
    C  += z1 * sC1 + z0 * sC0;
    int row0 = blockIdx.y * 128, col0 = blockIdx.x * BN;

    const int nch = K >> 5;

    auto load_chunk = [&](int ch, int st) {
        const float* Ak = A + (size_t)row0 * lda + ch * 32;
        const float* Bk = Bt + (size_t)col0 * ldb + ch * 32;
        uint32_t base = sb + st * STG * 4;
        #pragma unroll 4
        for (int idx = tid; idx < (128 + BN) * 8; idx += 256) {
            int h = idx & 7, kb = h >> 1, half = h & 1;
            if (idx < 1024) {
                int m = idx >> 3;
                uint32_t fo = kb * 1024 + ((m * 8 + half * 4) ^ (m & 4));
                CP16(base + fo * 4, Ak + (size_t)m * lda + h * 4);
            } else {
                int n = (idx >> 3) - 128;
                uint32_t fo = AF + kb * (BN * 8) + ((n * 8 + half * 4) ^ (n & 4));
                CP16(base + fo * 4, Bk + (size_t)n * ldb + h * 4);
            }
        }
    };

    for (int cc = 0; cc < S; cc++) {
        if (cc < nch) load_chunk(cc, cc);
        CP_COMMIT();
    }

    float acc[MF][NF][4];
    #pragma unroll
    for (int i = 0; i < MF; i++)
        #pragma unroll
        for (int j = 0; j < NF; j++)
            #pragma unroll
            for (int t = 0; t < 4; t++) acc[i][j][t] = 0.0f;

    const uint32_t* smu = (const uint32_t*)sm;

    for (int i = 0; i < nch; i++) {
        int st = i % S;
        CP_WAIT2();
        __syncthreads();
        const uint32_t* Au = smu + st * STG;
        const uint32_t* Bu = Au + AF;
        #pragma unroll
        for (int kb = 0; kb < 4; kb++) {
            uint32_t a[MF][4], b[NF][2];
            #pragma unroll
            for (int mf = 0; mf < MF; mf++) {
                int r = wm * (MF * 16) + mf * 16 + q;
                a[mf][0] = Au[kb * 1024 + ((r * 8 + c4) ^ (r & 4))];
                a[mf][1] = Au[kb * 1024 + (((r + 8) * 8 + c4) ^ ((r + 8) & 4))];
                a[mf][2] = Au[kb * 1024 + ((r * 8 + c4 + 4) ^ (r & 4))];
                a[mf][3] = Au[kb * 1024 + (((r + 8) * 8 + c4 + 4) ^ ((r + 8) & 4))];
            }
            #pragma unroll
            for (int nf = 0; nf < NF; nf++) {
                int n = wn * (NF * 8) + nf * 8 + q;
                b[nf][0] = Bu[kb * (BN * 8) + ((n * 8 + c4) ^ (n & 4))];
                b[nf][1] = Bu[kb * (BN * 8) + ((n * 8 + c4 + 4) ^ (n & 4))];
            }
            #pragma unroll
            for (int mf = 0; mf < MF; mf++)
                #pragma unroll
                for (int nf = 0; nf < NF; nf++)
                    mma8(acc[mf][nf], a[mf], b[nf]);
        }
        __syncthreads();
        int nx = i + S;
        if (nx < nch) load_chunk(nx, st);
        CP_COMMIT();
    }

    // epilogue: direct float2 stores
    #pragma unroll
    for (int mf = 0; mf < MF; mf++) {
        #pragma unroll
        for (int half = 0; half < 2; half++) {
            int m = row0 + wm * (MF * 16) + mf * 16 + q + half * 8;
            float* crow = C + (size_t)m * ldc;
            const float* rrow = res ? res + (size_t)m * ldr : nullptr;
            #pragma unroll
            for (int nf = 0; nf < NF; nf++) {
                int n = col0 + wn * (NF * 8) + nf * 8 + c4 * 2;
                float v0 = acc[mf][nf][half * 2 + 0] * scale;
                float v1 = acc[mf][nf][half * 2 + 1] * scale;
                if (bias) { v0 += bias[n]; v1 += bias[n + 1]; }
                if (GELU) {
                    v0 = 0.5f * v0 * (1.0f + erff(v0 * 0.70710678118654752f));
                    v1 = 0.5f * v1 * (1.0f + erff(v1 * 0.70710678118654752f));
                }
                if (ROUND) { v0 = rna_tf32(v0); v1 = rna_tf32(v1); }
                if (res) { v0 += rrow[n]; v1 += rrow[n + 1]; }
                *(float2*)(crow + n) = make_float2(v0, v1);
            }
        }
    }
}

// ---------------- LayerNorm (rounds output to tf32) --------------------------
template<bool ROUND>
__global__ void ln_kernel(const float* __restrict__ x, const float* __restrict__ g,
                          const float* __restrict__ be, float* __restrict__ out)
{
    __shared__ float sh[16];
    int row = blockIdx.x, t = threadIdx.x;
    const float* xr = x + (size_t)row * D;
    float v0 = xr[t], v1 = xr[t + 256], v2 = xr[t + 512];
    float s = v0 + v1 + v2, sq = v0*v0 + v1*v1 + v2*v2;
    #pragma unroll
    for (int o = 16; o; o >>= 1) {
        s  += __shfl_down_sync(0xffffffffu, s,  o);
        sq += __shfl_down_sync(0xffffffffu, sq, o);
    }
    int lane = t & 31, w = t >> 5;
    if (lane == 0) { sh[w] = s; sh[8 + w] = sq; }
    __syncthreads();
    if (t < 8) {
        s = sh[t]; sq = sh[8 + t];
        #pragma unroll
        for (int o = 4; o; o >>= 1) {
            s  += __shfl_down_sync(0xffu, s,  o);
            sq += __shfl_down_sync(0xffu, sq, o);
        }
        if (t == 0) {
            float mu = s * (1.0f / 768.0f);
            float var = sq * (1.0f / 768.0f) - mu * mu;
            sh[0] = mu; sh[1] = rsqrtf(var + 1e-5f);
        }
    }
    __syncthreads();
    float mu = sh[0], r = sh[1];
    float* orow = out + (size_t)row * D;
    float o0 = (v0 - mu) * r * g[t]       + be[t];
    float o1 = (v1 - mu) * r * g[t + 256] + be[t + 256];
    float o2 = (v2 - mu) * r * g[t + 512] + be[t + 512];
    if (ROUND) { o0 = rna_tf32(o0); o1 = rna_tf32(o1); o2 = rna_tf32(o2); }
    orow[t] = o0; orow[t + 256] = o1; orow[t + 512] = o2;
}

// ---------------- softmax over rows of 2048 (writes attention output) --------
__global__ void softmax_kernel(const float* __restrict__ e, float* __restrict__ attn)
{
    __shared__ float sh[8];
    size_t row = blockIdx.x;
    int t = threadIdx.x;
    const float4* er = (const float4*)(e + row * SEQ);
    float4 a = er[t], b = er[t + 256];
    float m = fmaxf(fmaxf(fmaxf(a.x, a.y), fmaxf(a.z, a.w)),
                    fmaxf(fmaxf(b.x, b.y), fmaxf(b.z, b.w)));
    #pragma unroll
    for (int o = 16; o; o >>= 1) m = fmaxf(m, __shfl_xor_sync(0xffffffffu, m, o));
    if ((t & 31) == 0) sh[t >> 5] = m;
    __syncthreads();
    if (t < 8) {
        m = sh[t];
        #pragma unroll
        for (int o = 4; o; o >>= 1) m = fmaxf(m, __shfl_xor_sync(0xffu, m, o));
        if (t == 0) sh[0] = m;
    }
    __syncthreads();
    m = sh[0];
    __syncthreads();
    a.x = __expf(a.x - m); a.y = __expf(a.y - m); a.z = __expf(a.z - m); a.w = __expf(a.w - m);
    b.x = __expf(b.x - m); b.y = __expf(b.y - m); b.z = __expf(b.z - m); b.w = __expf(b.w - m);
    float s = a.x + a.y + a.z + a.w + b.x + b.y + b.z + b.w;
    #pragma unroll
    for (int o = 16; o; o >>= 1) s += __shfl_xor_sync(0xffffffffu, s, o);
    if ((t & 31) == 0) sh[t >> 5] = s;
    __syncthreads();
    if (t < 8) {
        s = sh[t];
        #pragma unroll
        for (int o = 4; o; o >>= 1) s += __shfl_xor_sync(0xffu, s, o);
        if (t == 0) sh[0] = s;
    }
    __syncthreads();
    float inv = 1.0f / sh[0];
    a.x *= inv; a.y *= inv; a.z *= inv; a.w *= inv;
    b.x *= inv; b.y *= inv; b.z *= inv; b.w *= inv;
    float4* o4 = (float4*)(attn + row * SEQ);
    o4[t] = a; o4[t + 256] = b;
}

// ---------------- weight transpose + round -----------------------------------
__global__ void transpose_round(const float* __restrict__ in, float* __restrict__ out,
                                int K, int N)
{
    __shared__ float tile[32][33];
    int k0 = blockIdx.y * 32, n0 = blockIdx.x * 32;
    int tx = threadIdx.x, ty = threadIdx.y;
    #pragma unroll
    for (int i = ty; i < 32; i += 8)
        tile[i][tx] = in[(size_t)(k0 + i) * N + n0 + tx];
    __syncthreads();
    #pragma unroll
    for (int i = ty; i < 32; i += 8)
        out[(size_t)(n0 + i) * K + k0 + tx] = rna_tf32(tile[tx][i]);
}

// per-head v transpose: vT[z][n][k] = qkv[(b*SEQ+k)*2304 + 1536 + h*64 + n]
__global__ void vtrans_kernel(const float* __restrict__ qkv, float* __restrict__ vT)
{
    __shared__ float tile[32][33];
    int z = blockIdx.z, b = z / NH, h = z - b * NH;
    int k0 = blockIdx.x * 32, n0 = blockIdx.y * 32;
    int tx = threadIdx.x, ty = threadIdx.y;
    const float* src = qkv + (size_t)b * SEQ * (3 * D) + 2 * D + h * HD;
    #pragma unroll
    for (int i = ty; i < 32; i += 8)
        tile[i][tx] = src[(size_t)(k0 + i) * (3 * D) + n0 + tx];
    __syncthreads();
    float* dst = vT + (size_t)z * HD * SEQ;
    #pragma unroll
    for (int i = ty; i < 32; i += 8)
        dst[(size_t)(n0 + i) * SEQ + k0 + tx] = tile[tx][i];
}

__global__ void pack_bias(const float* bq, const float* bk, const float* bv, float* o)
{
    int j = blockIdx.x * 256 + threadIdx.x;
    if (j < 3 * D) o[j] = (j < D) ? bq[j] : (j < 2 * D) ? bk[j - D] : bv[j - 2 * D];
}

// ---------------- launch ------------------------------------------------------
extern "C" void kernel_launch(void* const* d_in, const int* in_sizes, int n_in,
                              void* d_out, int out_size)
{
    const float* x   = (const float*)d_in[0];
    const float* wq  = (const float*)d_in[1];  const float* bq  = (const float*)d_in[2];
    const float* wk  = (const float*)d_in[3];  const float* bk  = (const float*)d_in[4];
    const float* wv  = (const float*)d_in[5];  const float* bv  = (const float*)d_in[6];
    const float* wo  = (const float*)d_in[7];  const float* bo  = (const float*)d_in[8];
    const float* w1  = (const float*)d_in[9];  const float* b1  = (const float*)d_in[10];
    const float* w2  = (const float*)d_in[11]; const float* b2  = (const float*)d_in[12];
    const float* g1  = (const float*)d_in[13]; const float* be1 = (const float*)d_in[14];
    const float* g2  = (const float*)d_in[15]; const float* be2 = (const float*)d_in[16];

    float* out      = (float*)d_out;
    float* attn_out = out + (size_t)NROW * D;

    float *h1, *qkv, *wqkvT, *bqkv, *woT, *w1T, *w2T, *vT, *e, *ctx, *x2, *h2, *mlp;
    cudaGetSymbolAddress((void**)&h1,    g_h1);
    cudaGetSymbolAddress((void**)&qkv,   g_qkv);
    cudaGetSymbolAddress((void**)&wqkvT, g_wqkvT);
    cudaGetSymbolAddress((void**)&bqkv,  g_bqkv);
    cudaGetSymbolAddress((void**)&woT,   g_woT);
    cudaGetSymbolAddress((void**)&w1T,   g_w1T);
    cudaGetSymbolAddress((void**)&w2T,   g_w2T);
    cudaGetSymbolAddress((void**)&vT,    g_vT);
    cudaGetSymbolAddress((void**)&e,     g_e);
    cudaGetSymbolAddress((void**)&ctx,   g_ctx);
    cudaGetSymbolAddress((void**)&x2,    g_x2);
    cudaGetSymbolAddress((void**)&h2,    g_h2);
    cudaGetSymbolAddress((void**)&mlp,   g_mlp);

    const int SM128 = 3 * (128 * 32 + 128 * 32) * 4;   // 96 KB
    const int SM64  = 3 * (128 * 32 + 64 * 32) * 4;    // 72 KB
    cudaFuncSetAttribute(mm_tf32<128, false, true >, cudaFuncAttributeMaxDynamicSharedMemorySize, SM128);
    cudaFuncSetAttribute(mm_tf32<128, false, false>, cudaFuncAttributeMaxDynamicSharedMemorySize, SM128);
    cudaFuncSetAttribute(mm_tf32<128, true,  true >, cudaFuncAttributeMaxDynamicSharedMemorySize, SM128);
    cudaFuncSetAttribute(mm_tf32<64,  false, true >, cudaFuncAttributeMaxDynamicSharedMemorySize, SM64);

    dim3 tb(32, 8);
    transpose_round<<<dim3(D / 32, D / 32), tb>>>(wq, wqkvT,             D, D);
    transpose_round<<<dim3(D / 32, D / 32), tb>>>(wk, wqkvT + D * D,     D, D);
    transpose_round<<<dim3(D / 32, D / 32), tb>>>(wv, wqkvT + 2 * D * D, D, D);
    pack_bias<<<(3 * D + 255) / 256, 256>>>(bq, bk, bv, bqkv);
    ln_kernel<true><<<NROW, 256>>>(x, g1, be1, h1);

    // fused QKV: qkv[4096,2304] = h1 @ [wq|wk|wv] + bias  (rounded)
    mm_tf32<128, false, true><<<dim3(3 * D / 128, NROW / 128, 1), 256, SM128>>>(
        h1, D, 0, 0, wqkvT, D, 0, 0, qkv, 3 * D, 0, 0, bqkv, nullptr, 0, D, 1, 1.0f);

    // per-head v transpose -> vT[24][64][2048]
    vtrans_kernel<<<dim3(SEQ / 32, HD / 32, NHEAD), tb>>>(qkv, vT);

    // energy = q k^T / 8  (rounded; feeds softmax + ctx)
    mm_tf32<128, false, true><<<dim3(SEQ / 128, SEQ / 128, NHEAD), 256, SM128>>>(
        qkv,     3 * D, (size_t)SEQ * 3 * D, HD,
        qkv + D, 3 * D, (size_t)SEQ * 3 * D, HD,
        e, SEQ, (size_t)NH * SEQ * SEQ, (size_t)SEQ * SEQ,
        nullptr, nullptr, 0, HD, NH, 0.125f);

    // attention = softmax(energy)
    softmax_kernel<<<(unsigned)((size_t)NHEAD * SEQ), 256>>>(e, attn_out);

    // ctx = energy @ v  (reference bug preserved; rounded: feeds Wo)
    mm_tf32<64, false, true><<<dim3(1, SEQ / 128, NHEAD), 256, SM64>>>(
        e,  SEQ, (size_t)NH * SEQ * SEQ, (size_t)SEQ * SEQ,
        vT, SEQ, (size_t)NH * HD * SEQ,  (size_t)HD * SEQ,
        ctx, D, (size_t)SEQ * D, HD,
        nullptr, nullptr, 0, SEQ, NH, 1.0f);

    // x2 = x + ctx @ wo + bo
    transpose_round<<<dim3(D / 32, D / 32), tb>>>(wo, woT, D, D);
    mm_tf32<128, false, false><<<dim3(D / 128, NROW / 128, 1), 256, SM128>>>(
        ctx, D, 0, 0, woT, D, 0, 0, x2, D, 0, 0, bo, x, D, D, 1, 1.0f);

    // LN2 (rounded)
    ln_kernel<true><<<NROW, 256>>>(x2, g2, be2, h2);

    // mlp = gelu(h2 @ w1 + b1)  (rounded)
    transpose_round<<<dim3(F / 32, D / 32), tb>>>(w1, w1T, D, F);
    mm_tf32<128, true, true><<<dim3(F / 128, NROW / 128, 1), 256, SM128>>>(
        h2, D, 0, 0, w1T, D, 0, 0, mlp, F, 0, 0, b1, nullptr, 0, D, 1, 1.0f);

    // out = x2 + mlp @ w2 + b2
    transpose_round<<<dim3(D / 32, F / 32), tb>>>(w2, w2T, F, D);
    mm_tf32<128, false, false><<<dim3(D / 128, NROW / 128, 1), 256, SM128>>>(
        mlp, F, 0, 0, w2T, F, 0, 0, out, D, 0, 0, b2, x2, D, F, 1, 1.0f);
}

// round 6
// speedup vs baseline: 1.3052x; 1.1731x over previous
#include <cuda_runtime.h>
#include <math.h>
#include <stdint.h>

#define D    768
#define F    3072
#define SEQ  2048
#define BAT  2
#define NH   12
#define HD   64
#define NROW  (BAT*SEQ)   // 4096
#define NHEAD (BAT*NH)    // 24

// ---------------- scratch (device globals; allocations forbidden) -----------
__device__ float g_h1 [NROW*D];
__device__ float g_qkv[(size_t)NROW*3*D];
__device__ float g_wqkvT[3*D*D];
__device__ float g_bqkv[3*D];
__device__ float g_woT[D*D];
__device__ float g_w1T[D*F];
__device__ float g_w2T[D*F];
__device__ float g_vT [(size_t)NHEAD*HD*SEQ];
__device__ float g_e  [(size_t)NHEAD*SEQ*SEQ];   // 402 MB
__device__ float g_ctx[NROW*D];
__device__ float g_x2 [NROW*D];
__device__ float g_h2 [NROW*D];
__device__ float g_mlp[(size_t)NROW*F];

// ---------------- helpers ----------------------------------------------------
__device__ __forceinline__ uint32_t smem_u32(const void* p) {
    uint32_t a;
    asm("{ .reg .u64 t; cvta.to.shared.u64 t, %1; cvt.u32.u64 %0, t; }" : "=r"(a) : "l"(p));
    return a;
}
__device__ __forceinline__ float rna_tf32(float x) {
    float r;
    asm("cvt.rna.tf32.f32 %0, %1;" : "=f"(r) : "f"(x));
    return r;
}
__device__ __forceinline__ void mma8(float* d, const uint32_t* a, const uint32_t* b) {
    asm volatile(
        "mma.sync.aligned.m16n8k8.row.col.f32.tf32.tf32.f32 "
        "{%0,%1,%2,%3}, {%4,%5,%6,%7}, {%8,%9}, {%0,%1,%2,%3};"
        : "+f"(d[0]), "+f"(d[1]), "+f"(d[2]), "+f"(d[3])
        : "r"(a[0]), "r"(a[1]), "r"(a[2]), "r"(a[3]), "r"(b[0]), "r"(b[1]));
}
__device__ __forceinline__ void ldm_x4(uint32_t* r, uint32_t addr) {
    asm volatile("ldmatrix.sync.aligned.m8n8.x4.shared.b16 {%0,%1,%2,%3}, [%4];"
        : "=r"(r[0]), "=r"(r[1]), "=r"(r[2]), "=r"(r[3]) : "r"(addr));
}
#define CP16(dst, src) asm volatile("cp.async.cg.shared.global [%0], [%1], 16;" :: "r"(dst), "l"(src) : "memory")
#define CP_COMMIT()    asm volatile("cp.async.commit_group;" ::: "memory")
#define CP_WAIT2()     asm volatile("cp.async.wait_group 2;" ::: "memory")

// ---------------- tf32 mma.sync GEMM (ldmatrix fragments) --------------------
// C[M,N] = scale*(A[M,K] @ Bt[N,K]^T) (+bias) (GELU?) (round?) (+res)
// A, Bt K-major. CTA tile 128 x BN, 128 threads (4 warps, 2x2), BK=32, 3 stages.
// Smem per stage: A[4 kb][128 m][8 k] with 16B-group XOR swizzle, then B same.
template<int BN, bool GELU, bool ROUND>
__global__ void __launch_bounds__(128, 2) mm_tf32(
    const float* __restrict__ A, int lda, size_t sA1, size_t sA0,
    const float* __restrict__ Bt, int ldb, size_t sB1, size_t sB0,
    float* __restrict__ C, int ldc, size_t sC1, size_t sC0,
    const float* __restrict__ bias, const float* __restrict__ res, int ldr,
    int K, int zmod, float scale)
{
    constexpr int S   = 3;
    constexpr int WN  = BN / 2;
    constexpr int MF  = 4;              // m-frags per warp (64 rows)
    constexpr int NF  = WN / 8;         // n-frags per warp
    constexpr int AF  = 128 * 32;       // A floats per stage
    constexpr int BF  = BN * 32;
    constexpr int STG = AF + BF;

    extern __shared__ float sm[];
    const uint32_t sb = smem_u32(sm);

    int tid = threadIdx.x, w = tid >> 5, lane = tid & 31;
    int wm = w >> 1, wn = w & 1;
    int q = lane >> 2, c4 = lane & 3;

    int z = blockIdx.z, z1 = z / zmod, z0 = z - z1 * zmod;
    A  += z1 * sA1 + z0 * sA0;
    Bt += z1 * sB1 + z0 * sB0;
    C  += z1 * sC1 + z0 * sC0;
    int row0 = blockIdx.y * 128, col0 = blockIdx.x * BN;

    const int nch = K >> 5;

    auto load_chunk = [&](int ch, int st) {
        const float* Ak = A + (size_t)row0 * lda + ch * 32;
        const float* Bk = Bt + (size_t)col0 * ldb + ch * 32;
        uint32_t base = sb + st * STG * 4;
        #pragma unroll 4
        for (int idx = tid; idx < (128 + BN) * 8; idx += 128) {
            int h = idx & 7, kb = h >> 1, half = h & 1;
            if (idx < 1024) {
                int m = idx >> 3;
                uint32_t fo = kb * 1024 + ((m * 8 + half * 4) ^ (m & 4));
                CP16(base + fo * 4, Ak + (size_t)m * lda + h * 4);
            } else {
                int n = (idx >> 3) - 128;
                uint32_t fo = AF + kb * (BN * 8) + ((n * 8 + half * 4) ^ (n & 4));
                CP16(base + fo * 4, Bk + (size_t)n * ldb + h * 4);
            }
        }
    };

    // ldmatrix per-lane byte offsets within a stage (kb=0)
    int mat = lane >> 3, wrow = lane & 7;
    uint32_t aoff[MF];
    #pragma unroll
    for (int mf = 0; mf < MF; mf++) {
        int m = wm * 64 + mf * 16 + (mat & 1) * 8 + wrow;
        int h = mat >> 1;
        aoff[mf] = 4u * (uint32_t)((m * 8 + h * 4) ^ (m & 4));
    }
    uint32_t boff[NF / 2];
    #pragma unroll
    for (int p = 0; p < NF / 2; p++) {
        int n = wn * WN + (2 * p + (mat >> 1)) * 8 + wrow;
        int h = mat & 1;
        boff[p] = 4u * (uint32_t)((n * 8 + h * 4) ^ (n & 4));
    }

    for (int cc = 0; cc < S; cc++) {
        if (cc < nch) load_chunk(cc, cc);
        CP_COMMIT();
    }

    float acc[MF][NF][4];
    #pragma unroll
    for (int i = 0; i < MF; i++)
        #pragma unroll
        for (int j = 0; j < NF; j++)
            #pragma unroll
            for (int t = 0; t < 4; t++) acc[i][j][t] = 0.0f;

    for (int i = 0; i < nch; i++) {
        int st = i % S;
        CP_WAIT2();
        __syncthreads();
        uint32_t stA = sb + st * STG * 4;
        uint32_t stB = stA + AF * 4;
        #pragma unroll
        for (int kb = 0; kb < 4; kb++) {
            uint32_t abase = stA + kb * 4096;
            uint32_t bbase = stB + kb * (BN * 32);
            uint32_t a[MF][4], b[NF][2];
            #pragma unroll
            for (int mf = 0; mf < MF; mf++)
                ldm_x4(a[mf], abase + aoff[mf]);
            #pragma unroll
            for (int p = 0; p < NF / 2; p++)
                ldm_x4(&b[2 * p][0], bbase + boff[p]);
            #pragma unroll
            for (int mf = 0; mf < MF; mf++)
                #pragma unroll
                for (int nf = 0; nf < NF; nf++)
                    mma8(acc[mf][nf], a[mf], b[nf]);
        }
        __syncthreads();
        int nx = i + S;
        if (nx < nch) load_chunk(nx, st);
        CP_COMMIT();
    }

    // epilogue: direct float2 stores
    #pragma unroll
    for (int mf = 0; mf < MF; mf++) {
        #pragma unroll
        for (int half = 0; half < 2; half++) {
            int m = row0 + wm * 64 + mf * 16 + q + half * 8;
            float* crow = C + (size_t)m * ldc;
            const float* rrow = res ? res + (size_t)m * ldr : nullptr;
            #pragma unroll
            for (int nf = 0; nf < NF; nf++) {
                int n = col0 + wn * WN + nf * 8 + c4 * 2;
                float v0 = acc[mf][nf][half * 2 + 0] * scale;
                float v1 = acc[mf][nf][half * 2 + 1] * scale;
                if (bias) { v0 += bias[n]; v1 += bias[n + 1]; }
                if (GELU) {
                    v0 = 0.5f * v0 * (1.0f + erff(v0 * 0.70710678118654752f));
                    v1 = 0.5f * v1 * (1.0f + erff(v1 * 0.70710678118654752f));
                }
                if (ROUND) { v0 = rna_tf32(v0); v1 = rna_tf32(v1); }
                if (res) { v0 += rrow[n]; v1 += rrow[n + 1]; }
                *(float2*)(crow + n) = make_float2(v0, v1);
            }
        }
    }
}

// ---------------- LayerNorm (rounds output to tf32) --------------------------
template<bool ROUND>
__global__ void ln_kernel(const float* __restrict__ x, const float* __restrict__ g,
                          const float* __restrict__ be, float* __restrict__ out)
{
    __shared__ float sh[16];
    int row = blockIdx.x, t = threadIdx.x;
    const float* xr = x + (size_t)row * D;
    float v0 = xr[t], v1 = xr[t + 256], v2 = xr[t + 512];
    float s = v0 + v1 + v2, sq = v0*v0 + v1*v1 + v2*v2;
    #pragma unroll
    for (int o = 16; o; o >>= 1) {
        s  += __shfl_down_sync(0xffffffffu, s,  o);
        sq += __shfl_down_sync(0xffffffffu, sq, o);
    }
    int lane = t & 31, w = t >> 5;
    if (lane == 0) { sh[w] = s; sh[8 + w] = sq; }
    __syncthreads();
    if (t < 8) {
        s = sh[t]; sq = sh[8 + t];
        #pragma unroll
        for (int o = 4; o; o >>= 1) {
            s  += __shfl_down_sync(0xffu, s,  o);
            sq += __shfl_down_sync(0xffu, sq, o);
        }
        if (t == 0) {
            float mu = s * (1.0f / 768.0f);
            float var = sq * (1.0f / 768.0f) - mu * mu;
            sh[0] = mu; sh[1] = rsqrtf(var + 1e-5f);
        }
    }
    __syncthreads();
    float mu = sh[0], r = sh[1];
    float* orow = out + (size_t)row * D;
    float o0 = (v0 - mu) * r * g[t]       + be[t];
    float o1 = (v1 - mu) * r * g[t + 256] + be[t + 256];
    float o2 = (v2 - mu) * r * g[t + 512] + be[t + 512];
    if (ROUND) { o0 = rna_tf32(o0); o1 = rna_tf32(o1); o2 = rna_tf32(o2); }
    orow[t] = o0; orow[t + 256] = o1; orow[t + 512] = o2;
}

// ---------------- softmax over rows of 2048 (writes attention output) --------
__global__ void softmax_kernel(const float* __restrict__ e, float* __restrict__ attn)
{
    __shared__ float sh[8];
    size_t row = blockIdx.x;
    int t = threadIdx.x;
    const float4* er = (const float4*)(e + row * SEQ);
    float4 a = er[t], b = er[t + 256];
    float m = fmaxf(fmaxf(fmaxf(a.x, a.y), fmaxf(a.z, a.w)),
                    fmaxf(fmaxf(b.x, b.y), fmaxf(b.z, b.w)));
    #pragma unroll
    for (int o = 16; o; o >>= 1) m = fmaxf(m, __shfl_xor_sync(0xffffffffu, m, o));
    if ((t & 31) == 0) sh[t >> 5] = m;
    __syncthreads();
    if (t < 8) {
        m = sh[t];
        #pragma unroll
        for (int o = 4; o; o >>= 1) m = fmaxf(m, __shfl_xor_sync(0xffu, m, o));
        if (t == 0) sh[0] = m;
    }
    __syncthreads();
    m = sh[0];
    __syncthreads();
    a.x = __expf(a.x - m); a.y = __expf(a.y - m); a.z = __expf(a.z - m); a.w = __expf(a.w - m);
    b.x = __expf(b.x - m); b.y = __expf(b.y - m); b.z = __expf(b.z - m); b.w = __expf(b.w - m);
    float s = a.x + a.y + a.z + a.w + b.x + b.y + b.z + b.w;
    #pragma unroll
    for (int o = 16; o; o >>= 1) s += __shfl_xor_sync(0xffffffffu, s, o);
    if ((t & 31) == 0) sh[t >> 5] = s;
    __syncthreads();
    if (t < 8) {
        s = sh[t];
        #pragma unroll
        for (int o = 4; o; o >>= 1) s += __shfl_xor_sync(0xffu, s, o);
        if (t == 0) sh[0] = s;
    }
    __syncthreads();
    float inv = 1.0f / sh[0];
    a.x *= inv; a.y *= inv; a.z *= inv; a.w *= inv;
    b.x *= inv; b.y *= inv; b.z *= inv; b.w *= inv;
    float4* o4 = (float4*)(attn + row * SEQ);
    o4[t] = a; o4[t + 256] = b;
}

// ---------------- weight transpose + round -----------------------------------
__global__ void transpose_round(const float* __restrict__ in, float* __restrict__ out,
                                int K, int N)
{
    __shared__ float tile[32][33];
    int k0 = blockIdx.y * 32, n0 = blockIdx.x * 32;
    int tx = threadIdx.x, ty = threadIdx.y;
    #pragma unroll
    for (int i = ty; i < 32; i += 8)
        tile[i][tx] = in[(size_t)(k0 + i) * N + n0 + tx];
    __syncthreads();
    #pragma unroll
    for (int i = ty; i < 32; i += 8)
        out[(size_t)(n0 + i) * K + k0 + tx] = rna_tf32(tile[tx][i]);
}

// per-head v transpose: vT[z][n][k] = qkv[(b*SEQ+k)*2304 + 1536 + h*64 + n]
__global__ void vtrans_kernel(const float* __restrict__ qkv, float* __restrict__ vT)
{
    __shared__ float tile[32][33];
    int z = blockIdx.z, b = z / NH, h = z - b * NH;
    int k0 = blockIdx.x * 32, n0 = blockIdx.y * 32;
    int tx = threadIdx.x, ty = threadIdx.y;
    const float* src = qkv + (size_t)b * SEQ * (3 * D) + 2 * D + h * HD;
    #pragma unroll
    for (int i = ty; i < 32; i += 8)
        tile[i][tx] = src[(size_t)(k0 + i) * (3 * D) + n0 + tx];
    __syncthreads();
    float* dst = vT + (size_t)z * HD * SEQ;
    #pragma unroll
    for (int i = ty; i < 32; i += 8)
        dst[(size_t)(n0 + i) * SEQ + k0 + tx] = tile[tx][i];
}

__global__ void pack_bias(const float* bq, const float* bk, const float* bv, float* o)
{
    int j = blockIdx.x * 256 + threadIdx.x;
    if (j < 3 * D) o[j] = (j < D) ? bq[j] : (j < 2 * D) ? bk[j - D] : bv[j - 2 * D];
}

// ---------------- launch ------------------------------------------------------
extern "C" void kernel_launch(void* const* d_in, const int* in_sizes, int n_in,
                              void* d_out, int out_size)
{
    const float* x   = (const float*)d_in[0];
    const float* wq  = (const float*)d_in[1];  const float* bq  = (const float*)d_in[2];
    const float* wk  = (const float*)d_in[3];  const float* bk  = (const float*)d_in[4];
    const float* wv  = (const float*)d_in[5];  const float* bv  = (const float*)d_in[6];
    const float* wo  = (const float*)d_in[7];  const float* bo  = (const float*)d_in[8];
    const float* w1  = (const float*)d_in[9];  const float* b1  = (const float*)d_in[10];
    const float* w2  = (const float*)d_in[11]; const float* b2  = (const float*)d_in[12];
    const float* g1  = (const float*)d_in[13]; const float* be1 = (const float*)d_in[14];
    const float* g2  = (const float*)d_in[15]; const float* be2 = (const float*)d_in[16];

    float* out      = (float*)d_out;
    float* attn_out = out + (size_t)NROW * D;

    float *h1, *qkv, *wqkvT, *bqkv, *woT, *w1T, *w2T, *vT, *e, *ctx, *x2, *h2, *mlp;
    cudaGetSymbolAddress((void**)&h1,    g_h1);
    cudaGetSymbolAddress((void**)&qkv,   g_qkv);
    cudaGetSymbolAddress((void**)&wqkvT, g_wqkvT);
    cudaGetSymbolAddress((void**)&bqkv,  g_bqkv);
    cudaGetSymbolAddress((void**)&woT,   g_woT);
    cudaGetSymbolAddress((void**)&w1T,   g_w1T);
    cudaGetSymbolAddress((void**)&w2T,   g_w2T);
    cudaGetSymbolAddress((void**)&vT,    g_vT);
    cudaGetSymbolAddress((void**)&e,     g_e);
    cudaGetSymbolAddress((void**)&ctx,   g_ctx);
    cudaGetSymbolAddress((void**)&x2,    g_x2);
    cudaGetSymbolAddress((void**)&h2,    g_h2);
    cudaGetSymbolAddress((void**)&mlp,   g_mlp);

    const int SM128 = 3 * (128 * 32 + 128 * 32) * 4;   // 96 KB
    const int SM64  = 3 * (128 * 32 + 64 * 32) * 4;    // 72 KB
    cudaFuncSetAttribute(mm_tf32<128, false, true >, cudaFuncAttributeMaxDynamicSharedMemorySize, SM128);
    cudaFuncSetAttribute(mm_tf32<128, false, false>, cudaFuncAttributeMaxDynamicSharedMemorySize, SM128);
    cudaFuncSetAttribute(mm_tf32<128, true,  true >, cudaFuncAttributeMaxDynamicSharedMemorySize, SM128);
    cudaFuncSetAttribute(mm_tf32<64,  false, true >, cudaFuncAttributeMaxDynamicSharedMemorySize, SM64);

    dim3 tb(32, 8);
    transpose_round<<<dim3(D / 32, D / 32), tb>>>(wq, wqkvT,             D, D);
    transpose_round<<<dim3(D / 32, D / 32), tb>>>(wk, wqkvT + D * D,     D, D);
    transpose_round<<<dim3(D / 32, D / 32), tb>>>(wv, wqkvT + 2 * D * D, D, D);
    pack_bias<<<(3 * D + 255) / 256, 256>>>(bq, bk, bv, bqkv);
    ln_kernel<true><<<NROW, 256>>>(x, g1, be1, h1);

    // fused QKV: qkv[4096,2304] = h1 @ [wq|wk|wv] + bias  (rounded)
    mm_tf32<128, false, true><<<dim3(3 * D / 128, NROW / 128, 1), 128, SM128>>>(
        h1, D, 0, 0, wqkvT, D, 0, 0, qkv, 3 * D, 0, 0, bqkv, nullptr, 0, D, 1, 1.0f);

    // per-head v transpose -> vT[24][64][2048]
    vtrans_kernel<<<dim3(SEQ / 32, HD / 32, NHEAD), tb>>>(qkv, vT);

    // energy = q k^T / 8  (rounded; feeds softmax + ctx)
    mm_tf32<128, false, true><<<dim3(SEQ / 128, SEQ / 128, NHEAD), 128, SM128>>>(
        qkv,     3 * D, (size_t)SEQ * 3 * D, HD,
        qkv + D, 3 * D, (size_t)SEQ * 3 * D, HD,
        e, SEQ, (size_t)NH * SEQ * SEQ, (size_t)SEQ * SEQ,
        nullptr, nullptr, 0, HD, NH, 0.125f);

    // attention = softmax(energy)
    softmax_kernel<<<(unsigned)((size_t)NHEAD * SEQ), 256>>>(e, attn_out);

    // ctx = energy @ v  (reference bug preserved; rounded: feeds Wo)
    mm_tf32<64, false, true><<<dim3(1, SEQ / 128, NHEAD), 128, SM64>>>(
        e,  SEQ, (size_t)NH * SEQ * SEQ, (size_t)SEQ * SEQ,
        vT, SEQ, (size_t)NH * HD * SEQ,  (size_t)HD * SEQ,
        ctx, D, (size_t)SEQ * D, HD,
        nullptr, nullptr, 0, SEQ, NH, 1.0f);

    // x2 = x + ctx @ wo + bo
    transpose_round<<<dim3(D / 32, D / 32), tb>>>(wo, woT, D, D);
    mm_tf32<128, false, false><<<dim3(D / 128, NROW / 128, 1), 128, SM128>>>(
        ctx, D, 0, 0, woT, D, 0, 0, x2, D, 0, 0, bo, x, D, D, 1, 1.0f);

    // LN2 (rounded)
    ln_kernel<true><<<NROW, 256>>>(x2, g2, be2, h2);

    // mlp = gelu(h2 @ w1 + b1)  (rounded)
    transpose_round<<<dim3(F / 32, D / 32), tb>>>(w1, w1T, D, F);
    mm_tf32<128, true, true><<<dim3(F / 128, NROW / 128, 1), 128, SM128>>>(
        h2, D, 0, 0, w1T, D, 0, 0, mlp, F, 0, 0, b1, nullptr, 0, D, 1, 1.0f);

    // out = x2 + mlp @ w2 + b2
    transpose_round<<<dim3(D / 32, F / 32), tb>>>(w2, w2T, F, D);
    mm_tf32<128, false, false><<<dim3(D / 128, NROW / 128, 1), 128, SM128>>>(
        mlp, F, 0, 0, w2T, F, 0, 0, out, D, 0, 0, b2, x2, D, F, 1, 1.0f);
}

// round 7
// speedup vs baseline: 2.0456x; 1.5673x over previous
#include <cuda_runtime.h>
#include <cuda_fp16.h>
#include <math.h>
#include <stdint.h>

#define D    768
#define F    3072
#define SEQ  2048
#define BAT  2
#define NH   12
#define HD   64
#define NROW  (BAT*SEQ)   // 4096
#define NHEAD (BAT*NH)    // 24

// ---------------- scratch (device globals; allocations forbidden) -----------
__device__ __half g_h1 [NROW*D];
__device__ __half g_qkv[(size_t)NROW*3*D];
__device__ __half g_wqkvT[3*D*D];
__device__ float  g_bqkv[3*D];
__device__ __half g_woT[D*D];
__device__ __half g_w1T[D*F];
__device__ __half g_w2T[D*F];
__device__ __half g_vT [(size_t)NHEAD*HD*SEQ];
__device__ __half g_e  [(size_t)NHEAD*SEQ*SEQ];   // 201 MB
__device__ __half g_ctx[NROW*D];
__device__ float  g_x2 [NROW*D];
__device__ __half g_h2 [NROW*D];
__device__ __half g_mlp[(size_t)NROW*F];

// ---------------- helpers ----------------------------------------------------
__device__ __forceinline__ uint32_t smem_u32(const void* p) {
    uint32_t a;
    asm("{ .reg .u64 t; cvta.to.shared.u64 t, %1; cvt.u32.u64 %0, t; }" : "=r"(a) : "l"(p));
    return a;
}
__device__ __forceinline__ void mma16(float* d, const uint32_t* a, const uint32_t* b) {
    asm volatile(
        "mma.sync.aligned.m16n8k16.row.col.f32.f16.f16.f32 "
        "{%0,%1,%2,%3}, {%4,%5,%6,%7}, {%8,%9}, {%0,%1,%2,%3};"
        : "+f"(d[0]), "+f"(d[1]), "+f"(d[2]), "+f"(d[3])
        : "r"(a[0]), "r"(a[1]), "r"(a[2]), "r"(a[3]), "r"(b[0]), "r"(b[1]));
}
__device__ __forceinline__ void ldm_x4(uint32_t* r, uint32_t addr) {
    asm volatile("ldmatrix.sync.aligned.m8n8.x4.shared.b16 {%0,%1,%2,%3}, [%4];"
        : "=r"(r[0]), "=r"(r[1]), "=r"(r[2]), "=r"(r[3]) : "r"(addr));
}
#define CP16(dst, src) asm volatile("cp.async.cg.shared.global [%0], [%1], 16;" :: "r"(dst), "l"(src) : "memory")
#define CP_COMMIT()    asm volatile("cp.async.commit_group;" ::: "memory")
#define CP_WAIT3()     asm volatile("cp.async.wait_group 3;" ::: "memory")

// ---------------- fp16 mma.sync GEMM (fp32 accumulate) -----------------------
// C[M,N] = scale*(A[M,K] @ Bt[N,K]^T) (+bias) (GELU?) (+res)
// A, Bt fp16 K-major. CTA 128x BN, 128 thr (4 warps 2x2), BK=32, 4 stages.
// Smem per stage: A[2 kb][128 m][16 k] halves, 16B-unit XOR swizzle; B same.
template<int BN, bool GELU, bool OUTH>
__global__ void __launch_bounds__(128, 2) mm_half(
    const __half* __restrict__ A, int lda, size_t sA1, size_t sA0,
    const __half* __restrict__ Bt, int ldb, size_t sB1, size_t sB0,
    void* __restrict__ Cv, int ldc, size_t sC1, size_t sC0,
    const float* __restrict__ bias, const float* __restrict__ res, int ldr,
    int K, int zmod, float scale)
{
    constexpr int S   = 4;
    constexpr int WN  = BN / 2;
    constexpr int MF  = 4;               // m-frags (16 rows each) per warp
    constexpr int NF  = WN / 8;          // n-frags per warp
    constexpr int AB  = 128 * 64;        // A bytes per stage (128 x 32 half)
    constexpr int BB  = BN * 64;
    constexpr int STG = AB + BB;

    extern __shared__ char smc[];
    const uint32_t sb = smem_u32(smc);

    int tid = threadIdx.x, w = tid >> 5, lane = tid & 31;
    int wm = w >> 1, wn = w & 1;
    int q = lane >> 2, c4 = lane & 3;

    int z = blockIdx.z, z1 = z / zmod, z0 = z - z1 * zmod;
    A  += z1 * sA1 + z0 * sA0;
    Bt += z1 * sB1 + z0 * sB0;
    int row0 = blockIdx.y * 128, col0 = blockIdx.x * BN;

    const int nch = K >> 5;

    auto load_chunk = [&](int ch, int st) {
        const __half* Ak = A + (size_t)row0 * lda + ch * 32;
        const __half* Bk = Bt + (size_t)col0 * ldb + ch * 32;
        uint32_t base = sb + st * STG;
        #pragma unroll 4
        for (int idx = tid; idx < 512 + BN * 4; idx += 128) {
            int u = idx & 3, kb = u >> 1, h = u & 1;
            if (idx < 512) {
                int m = idx >> 2;
                uint32_t fo = kb * 4096 + (((uint32_t)(m * 32 + h * 16)) ^ ((m & 4) << 2));
                CP16(base + fo, Ak + (size_t)m * lda + kb * 16 + h * 8);
            } else {
                int n = (idx - 512) >> 2;
                uint32_t fo = AB + kb * (BN * 32) + (((uint32_t)(n * 32 + h * 16)) ^ ((n & 4) << 2));
                CP16(base + fo, Bk + (size_t)n * ldb + kb * 16 + h * 8);
            }
        }
    };

    // ldmatrix per-lane byte offsets (within kb=0 of a stage)
    int mat = lane >> 3, wrow = lane & 7;
    uint32_t aoff[MF];
    #pragma unroll
    for (int mf = 0; mf < MF; mf++) {
        int m = wm * 64 + mf * 16 + (mat & 1) * 8 + wrow;
        int h = mat >> 1;
        aoff[mf] = ((uint32_t)(m * 32 + h * 16)) ^ ((m & 4) << 2);
    }
    uint32_t boff[NF / 2];
    #pragma unroll
    for (int p = 0; p < NF / 2; p++) {
        int n = wn * WN + p * 16 + (mat >> 1) * 8 + wrow;
        int h = mat & 1;
        boff[p] = ((uint32_t)(n * 32 + h * 16)) ^ ((n & 4) << 2);
    }

    for (int cc = 0; cc < S; cc++) {
        if (cc < nch) load_chunk(cc, cc);
        CP_COMMIT();
    }

    float acc[MF][NF][4];
    #pragma unroll
    for (int i = 0; i < MF; i++)
        #pragma unroll
        for (int j = 0; j < NF; j++)
            #pragma unroll
            for (int t = 0; t < 4; t++) acc[i][j][t] = 0.0f;

    for (int i = 0; i < nch; i++) {
        int st = i % S;
        CP_WAIT3();
        __syncthreads();
        uint32_t stA = sb + st * STG;
        uint32_t stB = stA + AB;
        #pragma unroll
        for (int kb = 0; kb < 2; kb++) {
            uint32_t a[MF][4], b[NF][2];
            #pragma unroll
            for (int mf = 0; mf < MF; mf++)
                ldm_x4(a[mf], stA + kb * 4096 + aoff[mf]);
            #pragma unroll
            for (int p = 0; p < NF / 2; p++)
                ldm_x4(&b[2 * p][0], stB + kb * (BN * 32) + boff[p]);
            #pragma unroll
            for (int mf = 0; mf < MF; mf++)
                #pragma unroll
                for (int nf = 0; nf < NF; nf++)
                    mma16(acc[mf][nf], a[mf], b[nf]);
        }
        __syncthreads();
        int nx = i + S;
        if (nx < nch) load_chunk(nx, st);
        CP_COMMIT();
    }

    // epilogue
    #pragma unroll
    for (int mf = 0; mf < MF; mf++) {
        #pragma unroll
        for (int half_ = 0; half_ < 2; half_++) {
            int m = row0 + wm * 64 + mf * 16 + q + half_ * 8;
            size_t co = (size_t)z1 * sC1 + (size_t)z0 * sC0 + (size_t)m * ldc;
            const float* rrow = res ? res + (size_t)m * ldr : nullptr;
            #pragma unroll
            for (int nf = 0; nf < NF; nf++) {
                int n = col0 + wn * WN + nf * 8 + c4 * 2;
                float v0 = acc[mf][nf][half_ * 2 + 0] * scale;
                float v1 = acc[mf][nf][half_ * 2 + 1] * scale;
                if (bias) { v0 += bias[n]; v1 += bias[n + 1]; }
                if (GELU) {
                    v0 = 0.5f * v0 * (1.0f + erff(v0 * 0.70710678118654752f));
                    v1 = 0.5f * v1 * (1.0f + erff(v1 * 0.70710678118654752f));
                }
                if (OUTH) {
                    *(__half2*)((__half*)Cv + co + n) = __floats2half2_rn(v0, v1);
                } else {
                    if (res) { v0 += rrow[n]; v1 += rrow[n + 1]; }
                    *(float2*)((float*)Cv + co + n) = make_float2(v0, v1);
                }
            }
        }
    }
}

// ---------------- LayerNorm (fp16 output) -------------------------------------
__global__ void ln_kernel(const float* __restrict__ x, const float* __restrict__ g,
                          const float* __restrict__ be, __half* __restrict__ out)
{
    __shared__ float sh[16];
    int row = blockIdx.x, t = threadIdx.x;
    const float* xr = x + (size_t)row * D;
    float v0 = xr[t], v1 = xr[t + 256], v2 = xr[t + 512];
    float s = v0 + v1 + v2, sq = v0*v0 + v1*v1 + v2*v2;
    #pragma unroll
    for (int o = 16; o; o >>= 1) {
        s  += __shfl_down_sync(0xffffffffu, s,  o);
        sq += __shfl_down_sync(0xffffffffu, sq, o);
    }
    int lane = t & 31, w = t >> 5;
    if (lane == 0) { sh[w] = s; sh[8 + w] = sq; }
    __syncthreads();
    if (t < 8) {
        s = sh[t]; sq = sh[8 + t];
        #pragma unroll
        for (int o = 4; o; o >>= 1) {
            s  += __shfl_down_sync(0xffu, s,  o);
            sq += __shfl_down_sync(0xffu, sq, o);
        }
        if (t == 0) {
            float mu = s * (1.0f / 768.0f);
            float var = sq * (1.0f / 768.0f) - mu * mu;
            sh[0] = mu; sh[1] = rsqrtf(var + 1e-5f);
        }
    }
    __syncthreads();
    float mu = sh[0], r = sh[1];
    __half* orow = out + (size_t)row * D;
    orow[t]       = __float2half_rn((v0 - mu) * r * g[t]       + be[t]);
    orow[t + 256] = __float2half_rn((v1 - mu) * r * g[t + 256] + be[t + 256]);
    orow[t + 512] = __float2half_rn((v2 - mu) * r * g[t + 512] + be[t + 512]);
}

// ---------------- softmax over rows of 2048 (fp16 in, fp32 attention out) ----
__global__ void softmax_kernel(const __half* __restrict__ e, float* __restrict__ attn)
{
    __shared__ float sh[8];
    size_t row = blockIdx.x;
    int t = threadIdx.x;
    const uint4 u = ((const uint4*)(e + row * SEQ))[t];
    float2 f0 = __half22float2(*(const __half2*)&u.x);
    float2 f1 = __half22float2(*(const __half2*)(((const uint16_t*)&u.x) + 2));
    float2 f2 = __half22float2(*(const __half2*)&u.z);
    float2 f3 = __half22float2(*(const __half2*)(((const uint16_t*)&u.z) + 2));
    float f[8] = { f0.x, f0.y, f1.x, f1.y, f2.x, f2.y, f3.x, f3.y };
    float m = f[0];
    #pragma unroll
    for (int i = 1; i < 8; i++) m = fmaxf(m, f[i]);
    #pragma unroll
    for (int o = 16; o; o >>= 1) m = fmaxf(m, __shfl_xor_sync(0xffffffffu, m, o));
    if ((t & 31) == 0) sh[t >> 5] = m;
    __syncthreads();
    if (t < 8) {
        m = sh[t];
        #pragma unroll
        for (int o = 4; o; o >>= 1) m = fmaxf(m, __shfl_xor_sync(0xffu, m, o));
        if (t == 0) sh[0] = m;
    }
    __syncthreads();
    m = sh[0];
    __syncthreads();
    float s = 0.0f;
    #pragma unroll
    for (int i = 0; i < 8; i++) { f[i] = __expf(f[i] - m); s += f[i]; }
    #pragma unroll
    for (int o = 16; o; o >>= 1) s += __shfl_xor_sync(0xffffffffu, s, o);
    if ((t & 31) == 0) sh[t >> 5] = s;
    __syncthreads();
    if (t < 8) {
        s = sh[t];
        #pragma unroll
        for (int o = 4; o; o >>= 1) s += __shfl_xor_sync(0xffu, s, o);
        if (t == 0) sh[0] = s;
    }
    __syncthreads();
    float inv = 1.0f / sh[0];
    float4* o4 = (float4*)(attn + row * SEQ);
    o4[t * 2]     = make_float4(f[0] * inv, f[1] * inv, f[2] * inv, f[3] * inv);
    o4[t * 2 + 1] = make_float4(f[4] * inv, f[5] * inv, f[6] * inv, f[7] * inv);
}

// ---------------- weight transpose fp32 -> fp16 K-major -----------------------
__global__ void transpose_half(const float* __restrict__ in, __half* __restrict__ out,
                               int K, int N)
{
    __shared__ float tile[32][33];
    int k0 = blockIdx.y * 32, n0 = blockIdx.x * 32;
    int tx = threadIdx.x, ty = threadIdx.y;
    #pragma unroll
    for (int i = ty; i < 32; i += 8)
        tile[i][tx] = in[(size_t)(k0 + i) * N + n0 + tx];
    __syncthreads();
    #pragma unroll
    for (int i = ty; i < 32; i += 8)
        out[(size_t)(n0 + i) * K + k0 + tx] = __float2half_rn(tile[tx][i]);
}

// per-head v transpose: vT[z][n][k] = qkv[(b*SEQ+k)*2304 + 1536 + h*64 + n]
__global__ void vtrans_kernel(const __half* __restrict__ qkv, __half* __restrict__ vT)
{
    __shared__ __half tile[32][34];
    int z = blockIdx.z, b = z / NH, h = z - b * NH;
    int k0 = blockIdx.x * 32, n0 = blockIdx.y * 32;
    int tx = threadIdx.x, ty = threadIdx.y;
    const __half* src = qkv + (size_t)b * SEQ * (3 * D) + 2 * D + h * HD;
    #pragma unroll
    for (int i = ty; i < 32; i += 8)
        tile[i][tx] = src[(size_t)(k0 + i) * (3 * D) + n0 + tx];
    __syncthreads();
    __half* dst = vT + (size_t)z * HD * SEQ;
    #pragma unroll
    for (int i = ty; i < 32; i += 8)
        dst[(size_t)(n0 + i) * SEQ + k0 + tx] = tile[tx][i];
}

__global__ void pack_bias(const float* bq, const float* bk, const float* bv, float* o)
{
    int j = blockIdx.x * 256 + threadIdx.x;
    if (j < 3 * D) o[j] = (j < D) ? bq[j] : (j < 2 * D) ? bk[j - D] : bv[j - 2 * D];
}

// ---------------- launch ------------------------------------------------------
extern "C" void kernel_launch(void* const* d_in, const int* in_sizes, int n_in,
                              void* d_out, int out_size)
{
    const float* x   = (const float*)d_in[0];
    const float* wq  = (const float*)d_in[1];  const float* bq  = (const float*)d_in[2];
    const float* wk  = (const float*)d_in[3];  const float* bk  = (const float*)d_in[4];
    const float* wv  = (const float*)d_in[5];  const float* bv  = (const float*)d_in[6];
    const float* wo  = (const float*)d_in[7];  const float* bo  = (const float*)d_in[8];
    const float* w1  = (const float*)d_in[9];  const float* b1  = (const float*)d_in[10];
    const float* w2  = (const float*)d_in[11]; const float* b2  = (const float*)d_in[12];
    const float* g1  = (const float*)d_in[13]; const float* be1 = (const float*)d_in[14];
    const float* g2  = (const float*)d_in[15]; const float* be2 = (const float*)d_in[16];

    float* out      = (float*)d_out;
    float* attn_out = out + (size_t)NROW * D;

    __half *h1, *qkv, *wqkvT, *woT, *w1T, *w2T, *vT, *e, *ctx, *h2, *mlp;
    float *bqkv, *x2;
    cudaGetSymbolAddress((void**)&h1,    g_h1);
    cudaGetSymbolAddress((void**)&qkv,   g_qkv);
    cudaGetSymbolAddress((void**)&wqkvT, g_wqkvT);
    cudaGetSymbolAddress((void**)&bqkv,  g_bqkv);
    cudaGetSymbolAddress((void**)&woT,   g_woT);
    cudaGetSymbolAddress((void**)&w1T,   g_w1T);
    cudaGetSymbolAddress((void**)&w2T,   g_w2T);
    cudaGetSymbolAddress((void**)&vT,    g_vT);
    cudaGetSymbolAddress((void**)&e,     g_e);
    cudaGetSymbolAddress((void**)&ctx,   g_ctx);
    cudaGetSymbolAddress((void**)&x2,    g_x2);
    cudaGetSymbolAddress((void**)&h2,    g_h2);
    cudaGetSymbolAddress((void**)&mlp,   g_mlp);

    const int SM128 = 4 * (128 * 64 + 128 * 64);   // 64 KB
    const int SM64  = 4 * (128 * 64 + 64 * 64);    // 48 KB
    cudaFuncSetAttribute(mm_half<128, false, true >, cudaFuncAttributeMaxDynamicSharedMemorySize, SM128);
    cudaFuncSetAttribute(mm_half<128, false, false>, cudaFuncAttributeMaxDynamicSharedMemorySize, SM128);
    cudaFuncSetAttribute(mm_half<128, true,  true >, cudaFuncAttributeMaxDynamicSharedMemorySize, SM128);
    cudaFuncSetAttribute(mm_half<64,  false, true >, cudaFuncAttributeMaxDynamicSharedMemorySize, SM64);

    dim3 tb(32, 8);
    transpose_half<<<dim3(D / 32, D / 32), tb>>>(wq, wqkvT,             D, D);
    transpose_half<<<dim3(D / 32, D / 32), tb>>>(wk, wqkvT + D * D,     D, D);
    transpose_half<<<dim3(D / 32, D / 32), tb>>>(wv, wqkvT + 2 * D * D, D, D);
    pack_bias<<<(3 * D + 255) / 256, 256>>>(bq, bk, bv, bqkv);
    ln_kernel<<<NROW, 256>>>(x, g1, be1, h1);

    // fused QKV: qkv[4096,2304] = h1 @ [wq|wk|wv] + bias   (fp16 out)
    mm_half<128, false, true><<<dim3(3 * D / 128, NROW / 128, 1), 128, SM128>>>(
        h1, D, 0, 0, wqkvT, D, 0, 0, qkv, 3 * D, 0, 0, bqkv, nullptr, 0, D, 1, 1.0f);

    // per-head v transpose -> vT[24][64][2048]
    vtrans_kernel<<<dim3(SEQ / 32, HD / 32, NHEAD), tb>>>(qkv, vT);

    // energy = q k^T / 8   (fp16 out; feeds softmax + ctx)
    mm_half<128, false, true><<<dim3(SEQ / 128, SEQ / 128, NHEAD), 128, SM128>>>(
        qkv,     3 * D, (size_t)SEQ * 3 * D, HD,
        qkv + D, 3 * D, (size_t)SEQ * 3 * D, HD,
        e, SEQ, (size_t)NH * SEQ * SEQ, (size_t)SEQ * SEQ,
        nullptr, nullptr, 0, HD, NH, 0.125f);

    // attention = softmax(energy)
    softmax_kernel<<<(unsigned)((size_t)NHEAD * SEQ), 256>>>(e, attn_out);

    // ctx = energy @ v  (reference bug preserved; fp16 out)
    mm_half<64, false, true><<<dim3(1, SEQ / 128, NHEAD), 128, SM64>>>(
        e,  SEQ, (size_t)NH * SEQ * SEQ, (size_t)SEQ * SEQ,
        vT, SEQ, (size_t)NH * HD * SEQ,  (size_t)HD * SEQ,
        ctx, D, (size_t)SEQ * D, HD,
        nullptr, nullptr, 0, SEQ, NH, 1.0f);

    // x2 = x + ctx @ wo + bo   (fp32 out)
    transpose_half<<<dim3(D / 32, D / 32), tb>>>(wo, woT, D, D);
    mm_half<128, false, false><<<dim3(D / 128, NROW / 128, 1), 128, SM128>>>(
        ctx, D, 0, 0, woT, D, 0, 0, x2, D, 0, 0, bo, x, D, D, 1, 1.0f);

    // LN2 (fp16 out)
    ln_kernel<<<NROW, 256>>>(x2, g2, be2, h2);

    // mlp = gelu(h2 @ w1 + b1)   (fp16 out)
    transpose_half<<<dim3(F / 32, D / 32), tb>>>(w1, w1T, D, F);
    mm_half<128, true, true><<<dim3(F / 128, NROW / 128, 1), 128, SM128>>>(
        h2, D, 0, 0, w1T, D, 0, 0, mlp, F, 0, 0, b1, nullptr, 0, D, 1, 1.0f);

    // out = x2 + mlp @ w2 + b2   (fp32 out)
    transpose_half<<<dim3(D / 32, F / 32), tb>>>(w2, w2T, F, D);
    mm_half<128, false, false><<<dim3(D / 128, NROW / 128, 1), 128, SM128>>>(
        mlp, F, 0, 0, w2T, F, 0, 0, out, D, 0, 0, b2, x2, D, F, 1, 1.0f);
}

// round 8
// speedup vs baseline: 2.2104x; 1.0805x over previous
#include <cuda_runtime.h>
#include <cuda_fp16.h>
#include <math.h>
#include <stdint.h>

#define D    768
#define F    3072
#define SEQ  2048
#define BAT  2
#define NH   12
#define HD   64
#define NROW  (BAT*SEQ)   // 4096
#define NHEAD (BAT*NH)    // 24

// ---------------- scratch (device globals; allocations forbidden) -----------
__device__ __half g_h1 [NROW*D];
__device__ __half g_qkv[(size_t)NROW*3*D];
__device__ __half g_wqkvT[3*D*D];
__device__ float  g_bqkv[3*D];
__device__ __half g_woT[D*D];
__device__ __half g_w1T[D*F];
__device__ __half g_w2T[D*F];
__device__ __half g_e  [(size_t)NHEAD*SEQ*SEQ];   // 201 MB
__device__ float  g_ktvp[(size_t)NHEAD*16*HD*HD]; // kTv partials
__device__ __half g_ktvT[(size_t)NHEAD*HD*HD];    // kTv transposed, fp16
__device__ __half g_ctx[NROW*D];
__device__ float  g_x2 [NROW*D];
__device__ __half g_h2 [NROW*D];
__device__ __half g_mlp[(size_t)NROW*F];

// ---------------- helpers ----------------------------------------------------
__device__ __forceinline__ uint32_t smem_u32(const void* p) {
    uint32_t a;
    asm("{ .reg .u64 t; cvta.to.shared.u64 t, %1; cvt.u32.u64 %0, t; }" : "=r"(a) : "l"(p));
    return a;
}
__device__ __forceinline__ void mma16(float* d, const uint32_t* a, const uint32_t* b) {
    asm volatile(
        "mma.sync.aligned.m16n8k16.row.col.f32.f16.f16.f32 "
        "{%0,%1,%2,%3}, {%4,%5,%6,%7}, {%8,%9}, {%0,%1,%2,%3};"
        : "+f"(d[0]), "+f"(d[1]), "+f"(d[2]), "+f"(d[3])
        : "r"(a[0]), "r"(a[1]), "r"(a[2]), "r"(a[3]), "r"(b[0]), "r"(b[1]));
}
__device__ __forceinline__ void ldm_x4(uint32_t* r, uint32_t addr) {
    asm volatile("ldmatrix.sync.aligned.m8n8.x4.shared.b16 {%0,%1,%2,%3}, [%4];"
        : "=r"(r[0]), "=r"(r[1]), "=r"(r[2]), "=r"(r[3]) : "r"(addr));
}
#define CP16(dst, src) asm volatile("cp.async.cg.shared.global [%0], [%1], 16;" :: "r"(dst), "l"(src) : "memory")
#define CP_COMMIT()    asm volatile("cp.async.commit_group;" ::: "memory")
#define CP_WAIT3()     asm volatile("cp.async.wait_group 3;" ::: "memory")

// ---------------- fp16 mma.sync GEMM (fp32 accumulate) -----------------------
// C[M,N] = scale*(A[M,K] @ Bt[N,K]^T) (+bias) (GELU?) (+res)
// A, Bt fp16 K-major. CTA 128x BN, 128 thr (4 warps 2x2), BK=32, 4 stages.
template<int BN, bool GELU, bool OUTH>
__global__ void __launch_bounds__(128, 2) mm_half(
    const __half* __restrict__ A, int lda, size_t sA1, size_t sA0,
    const __half* __restrict__ Bt, int ldb, size_t sB1, size_t sB0,
    void* __restrict__ Cv, int ldc, size_t sC1, size_t sC0,
    const float* __restrict__ bias, const float* __restrict__ res, int ldr,
    int K, int zmod, float scale)
{
    constexpr int S   = 4;
    constexpr int WN  = BN / 2;
    constexpr int MF  = 4;
    constexpr int NF  = WN / 8;
    constexpr int AB  = 128 * 64;
    constexpr int BB  = BN * 64;
    constexpr int STG = AB + BB;

    extern __shared__ char smc[];
    const uint32_t sb = smem_u32(smc);

    int tid = threadIdx.x, w = tid >> 5, lane = tid & 31;
    int wm = w >> 1, wn = w & 1;
    int q = lane >> 2, c4 = lane & 3;

    int z = blockIdx.z, z1 = z / zmod, z0 = z - z1 * zmod;
    A  += z1 * sA1 + z0 * sA0;
    Bt += z1 * sB1 + z0 * sB0;
    int row0 = blockIdx.y * 128, col0 = blockIdx.x * BN;

    const int nch = K >> 5;

    auto load_chunk = [&](int ch, int st) {
        const __half* Ak = A + (size_t)row0 * lda + ch * 32;
        const __half* Bk = Bt + (size_t)col0 * ldb + ch * 32;
        uint32_t base = sb + st * STG;
        #pragma unroll 4
        for (int idx = tid; idx < 512 + BN * 4; idx += 128) {
            int u = idx & 3, kb = u >> 1, h = u & 1;
            if (idx < 512) {
                int m = idx >> 2;
                uint32_t fo = kb * 4096 + (((uint32_t)(m * 32 + h * 16)) ^ ((m & 4) << 2));
                CP16(base + fo, Ak + (size_t)m * lda + kb * 16 + h * 8);
            } else {
                int n = (idx - 512) >> 2;
                uint32_t fo = AB + kb * (BN * 32) + (((uint32_t)(n * 32 + h * 16)) ^ ((n & 4) << 2));
                CP16(base + fo, Bk + (size_t)n * ldb + kb * 16 + h * 8);
            }
        }
    };

    int mat = lane >> 3, wrow = lane & 7;
    uint32_t aoff[MF];
    #pragma unroll
    for (int mf = 0; mf < MF; mf++) {
        int m = wm * 64 + mf * 16 + (mat & 1) * 8 + wrow;
        int h = mat >> 1;
        aoff[mf] = ((uint32_t)(m * 32 + h * 16)) ^ ((m & 4) << 2);
    }
    uint32_t boff[NF / 2];
    #pragma unroll
    for (int p = 0; p < NF / 2; p++) {
        int n = wn * WN + p * 16 + (mat >> 1) * 8 + wrow;
        int h = mat & 1;
        boff[p] = ((uint32_t)(n * 32 + h * 16)) ^ ((n & 4) << 2);
    }

    for (int cc = 0; cc < S; cc++) {
        if (cc < nch) load_chunk(cc, cc);
        CP_COMMIT();
    }

    float acc[MF][NF][4];
    #pragma unroll
    for (int i = 0; i < MF; i++)
        #pragma unroll
        for (int j = 0; j < NF; j++)
            #pragma unroll
            for (int t = 0; t < 4; t++) acc[i][j][t] = 0.0f;

    for (int i = 0; i < nch; i++) {
        int st = i % S;
        CP_WAIT3();
        __syncthreads();
        uint32_t stA = sb + st * STG;
        uint32_t stB = stA + AB;
        #pragma unroll
        for (int kb = 0; kb < 2; kb++) {
            uint32_t a[MF][4], b[NF][2];
            #pragma unroll
            for (int mf = 0; mf < MF; mf++)
                ldm_x4(a[mf], stA + kb * 4096 + aoff[mf]);
            #pragma unroll
            for (int p = 0; p < NF / 2; p++)
                ldm_x4(&b[2 * p][0], stB + kb * (BN * 32) + boff[p]);
            #pragma unroll
            for (int mf = 0; mf < MF; mf++)
                #pragma unroll
                for (int nf = 0; nf < NF; nf++)
                    mma16(acc[mf][nf], a[mf], b[nf]);
        }
        __syncthreads();
        int nx = i + S;
        if (nx < nch) load_chunk(nx, st);
        CP_COMMIT();
    }

    #pragma unroll
    for (int mf = 0; mf < MF; mf++) {
        #pragma unroll
        for (int half_ = 0; half_ < 2; half_++) {
            int m = row0 + wm * 64 + mf * 16 + q + half_ * 8;
            size_t co = (size_t)z1 * sC1 + (size_t)z0 * sC0 + (size_t)m * ldc;
            const float* rrow = res ? res + (size_t)m * ldr : nullptr;
            #pragma unroll
            for (int nf = 0; nf < NF; nf++) {
                int n = col0 + wn * WN + nf * 8 + c4 * 2;
                float v0 = acc[mf][nf][half_ * 2 + 0] * scale;
                float v1 = acc[mf][nf][half_ * 2 + 1] * scale;
                if (bias) { v0 += bias[n]; v1 += bias[n + 1]; }
                if (GELU) {
                    v0 = 0.5f * v0 * (1.0f + erff(v0 * 0.70710678118654752f));
                    v1 = 0.5f * v1 * (1.0f + erff(v1 * 0.70710678118654752f));
                }
                if (OUTH) {
                    *(__half2*)((__half*)Cv + co + n) = __floats2half2_rn(v0, v1);
                } else {
                    if (res) { v0 += rrow[n]; v1 += rrow[n + 1]; }
                    *(float2*)((float*)Cv + co + n) = make_float2(v0, v1);
                }
            }
        }
    }
}

// ---------------- kTv partials: P[z][slice] = k_slice^T @ v_slice ------------
// grid (16, 24), 256 thr, 64KB dyn smem. slice = 128 seq rows.
__global__ void ktv_partial(const __half* __restrict__ qkv, float* __restrict__ part)
{
    extern __shared__ float s[];
    float* ks = s;              // [128][64]
    float* vs = s + 128 * 64;   // [128][64]
    int z = blockIdx.y, b = z / NH, h = z - b * NH;
    int s0 = blockIdx.x * 128;
    int tid = threadIdx.x;
    const __half* kbase = qkv + (size_t)(b * SEQ + s0) * (3 * D) + D + h * HD;
    const __half* vbase = kbase + D;
    for (int i = tid; i < 128 * 16; i += 256) {
        int r = i >> 4, c = (i & 15) * 4;
        uint2 kk = *(const uint2*)(kbase + (size_t)r * (3 * D) + c);
        uint2 vv = *(const uint2*)(vbase + (size_t)r * (3 * D) + c);
        float2 k0 = __half22float2(*(__half2*)&kk.x), k1 = __half22float2(*(__half2*)&kk.y);
        float2 v0 = __half22float2(*(__half2*)&vv.x), v1 = __half22float2(*(__half2*)&vv.y);
        float* kd = ks + r * 64 + c;
        kd[0] = k0.x; kd[1] = k0.y; kd[2] = k1.x; kd[3] = k1.y;
        float* vd = vs + r * 64 + c;
        vd[0] = v0.x; vd[1] = v0.y; vd[2] = v1.x; vd[3] = v1.y;
    }
    __syncthreads();
    int tx = tid & 15, ty = tid >> 4;
    float acc[4][4] = {};
    for (int ss = 0; ss < 128; ss++) {
        float4 kv = *(const float4*)(ks + ss * 64 + ty * 4);
        float4 vv = *(const float4*)(vs + ss * 64 + tx * 4);
        const float ka[4] = { kv.x, kv.y, kv.z, kv.w };
        const float va[4] = { vv.x, vv.y, vv.z, vv.w };
        #pragma unroll
        for (int i = 0; i < 4; i++)
            #pragma unroll
            for (int j = 0; j < 4; j++)
                acc[i][j] = fmaf(ka[i], va[j], acc[i][j]);
    }
    float* pout = part + ((size_t)z * 16 + blockIdx.x) * (HD * HD);
    #pragma unroll
    for (int i = 0; i < 4; i++)
        #pragma unroll
        for (int j = 0; j < 4; j++)
            pout[(ty * 4 + i) * 64 + tx * 4 + j] = acc[i][j];
}

// reduce 16 partials -> kTvT[z][d2][d1] fp16
__global__ void ktv_reduce(const float* __restrict__ part, __half* __restrict__ ktvT)
{
    int z = blockIdx.x, tid = threadIdx.x;
    for (int i = tid; i < HD * HD; i += 256) {
        int d1 = i >> 6, d2 = i & 63;
        float sum = 0.0f;
        #pragma unroll
        for (int p = 0; p < 16; p++)
            sum += part[((size_t)z * 16 + p) * (HD * HD) + i];
        ktvT[(size_t)z * (HD * HD) + d2 * 64 + d1] = __float2half_rn(sum);
    }
}

// ---------------- LayerNorm (fp16 output) -------------------------------------
__global__ void ln_kernel(const float* __restrict__ x, const float* __restrict__ g,
                          const float* __restrict__ be, __half* __restrict__ out)
{
    __shared__ float sh[16];
    int row = blockIdx.x, t = threadIdx.x;
    const float* xr = x + (size_t)row * D;
    float v0 = xr[t], v1 = xr[t + 256], v2 = xr[t + 512];
    float s = v0 + v1 + v2, sq = v0*v0 + v1*v1 + v2*v2;
    #pragma unroll
    for (int o = 16; o; o >>= 1) {
        s  += __shfl_down_sync(0xffffffffu, s,  o);
        sq += __shfl_down_sync(0xffffffffu, sq, o);
    }
    int lane = t & 31, w = t >> 5;
    if (lane == 0) { sh[w] = s; sh[8 + w] = sq; }
    __syncthreads();
    if (t < 8) {
        s = sh[t]; sq = sh[8 + t];
        #pragma unroll
        for (int o = 4; o; o >>= 1) {
            s  += __shfl_down_sync(0xffu, s,  o);
            sq += __shfl_down_sync(0xffu, sq, o);
        }
        if (t == 0) {
            float mu = s * (1.0f / 768.0f);
            float var = sq * (1.0f / 768.0f) - mu * mu;
            sh[0] = mu; sh[1] = rsqrtf(var + 1e-5f);
        }
    }
    __syncthreads();
    float mu = sh[0], r = sh[1];
    __half* orow = out + (size_t)row * D;
    orow[t]       = __float2half_rn((v0 - mu) * r * g[t]       + be[t]);
    orow[t + 256] = __float2half_rn((v1 - mu) * r * g[t + 256] + be[t + 256]);
    orow[t + 512] = __float2half_rn((v2 - mu) * r * g[t + 512] + be[t + 512]);
}

// ---------------- softmax over rows of 2048 (fp16 in, fp32 attention out) ----
__global__ void softmax_kernel(const __half* __restrict__ e, float* __restrict__ attn)
{
    __shared__ float sh[8];
    size_t row = blockIdx.x;
    int t = threadIdx.x;
    const uint4 u = ((const uint4*)(e + row * SEQ))[t];
    float2 f0 = __half22float2(*(const __half2*)&u.x);
    float2 f1 = __half22float2(*(const __half2*)&u.y);
    float2 f2 = __half22float2(*(const __half2*)&u.z);
    float2 f3 = __half22float2(*(const __half2*)&u.w);
    float f[8] = { f0.x, f0.y, f1.x, f1.y, f2.x, f2.y, f3.x, f3.y };
    float m = f[0];
    #pragma unroll
    for (int i = 1; i < 8; i++) m = fmaxf(m, f[i]);
    #pragma unroll
    for (int o = 16; o; o >>= 1) m = fmaxf(m, __shfl_xor_sync(0xffffffffu, m, o));
    if ((t & 31) == 0) sh[t >> 5] = m;
    __syncthreads();
    if (t < 8) {
        m = sh[t];
        #pragma unroll
        for (int o = 4; o; o >>= 1) m = fmaxf(m, __shfl_xor_sync(0xffu, m, o));
        if (t == 0) sh[0] = m;
    }
    __syncthreads();
    m = sh[0];
    __syncthreads();
    float s = 0.0f;
    #pragma unroll
    for (int i = 0; i < 8; i++) { f[i] = __expf(f[i] - m); s += f[i]; }
    #pragma unroll
    for (int o = 16; o; o >>= 1) s += __shfl_xor_sync(0xffffffffu, s, o);
    if ((t & 31) == 0) sh[t >> 5] = s;
    __syncthreads();
    if (t < 8) {
        s = sh[t];
        #pragma unroll
        for (int o = 4; o; o >>= 1) s += __shfl_xor_sync(0xffu, s, o);
        if (t == 0) sh[0] = s;
    }
    __syncthreads();
    float inv = 1.0f / sh[0];
    float4* o4 = (float4*)(attn + row * SEQ);
    o4[t * 2]     = make_float4(f[0] * inv, f[1] * inv, f[2] * inv, f[3] * inv);
    o4[t * 2 + 1] = make_float4(f[4] * inv, f[5] * inv, f[6] * inv, f[7] * inv);
}

// ---------------- weight transpose fp32 -> fp16 K-major -----------------------
__global__ void transpose_half(const float* __restrict__ in, __half* __restrict__ out,
                               int K, int N)
{
    __shared__ float tile[32][33];
    int k0 = blockIdx.y * 32, n0 = blockIdx.x * 32;
    int tx = threadIdx.x, ty = threadIdx.y;
    #pragma unroll
    for (int i = ty; i < 32; i += 8)
        tile[i][tx] = in[(size_t)(k0 + i) * N + n0 + tx];
    __syncthreads();
    #pragma unroll
    for (int i = ty; i < 32; i += 8)
        out[(size_t)(n0 + i) * K + k0 + tx] = __float2half_rn(tile[tx][i]);
}

__global__ void pack_bias(const float* bq, const float* bk, const float* bv, float* o)
{
    int j = blockIdx.x * 256 + threadIdx.x;
    if (j < 3 * D) o[j] = (j < D) ? bq[j] : (j < 2 * D) ? bk[j - D] : bv[j - 2 * D];
}

// ---------------- launch ------------------------------------------------------
extern "C" void kernel_launch(void* const* d_in, const int* in_sizes, int n_in,
                              void* d_out, int out_size)
{
    const float* x   = (const float*)d_in[0];
    const float* wq  = (const float*)d_in[1];  const float* bq  = (const float*)d_in[2];
    const float* wk  = (const float*)d_in[3];  const float* bk  = (const float*)d_in[4];
    const float* wv  = (const float*)d_in[5];  const float* bv  = (const float*)d_in[6];
    const float* wo  = (const float*)d_in[7];  const float* bo  = (const float*)d_in[8];
    const float* w1  = (const float*)d_in[9];  const float* b1  = (const float*)d_in[10];
    const float* w2  = (const float*)d_in[11]; const float* b2  = (const float*)d_in[12];
    const float* g1  = (const float*)d_in[13]; const float* be1 = (const float*)d_in[14];
    const float* g2  = (const float*)d_in[15]; const float* be2 = (const float*)d_in[16];

    float* out      = (float*)d_out;
    float* attn_out = out + (size_t)NROW * D;

    __half *h1, *qkv, *wqkvT, *woT, *w1T, *w2T, *e, *ktvT, *ctx, *h2, *mlp;
    float *bqkv, *ktvp, *x2;
    cudaGetSymbolAddress((void**)&h1,    g_h1);
    cudaGetSymbolAddress((void**)&qkv,   g_qkv);
    cudaGetSymbolAddress((void**)&wqkvT, g_wqkvT);
    cudaGetSymbolAddress((void**)&bqkv,  g_bqkv);
    cudaGetSymbolAddress((void**)&woT,   g_woT);
    cudaGetSymbolAddress((void**)&w1T,   g_w1T);
    cudaGetSymbolAddress((void**)&w2T,   g_w2T);
    cudaGetSymbolAddress((void**)&e,     g_e);
    cudaGetSymbolAddress((void**)&ktvp,  g_ktvp);
    cudaGetSymbolAddress((void**)&ktvT,  g_ktvT);
    cudaGetSymbolAddress((void**)&ctx,   g_ctx);
    cudaGetSymbolAddress((void**)&x2,    g_x2);
    cudaGetSymbolAddress((void**)&h2,    g_h2);
    cudaGetSymbolAddress((void**)&mlp,   g_mlp);

    const int SM128 = 4 * (128 * 64 + 128 * 64);   // 64 KB
    const int SM64  = 4 * (128 * 64 + 64 * 64);    // 48 KB
    const int SMKTV = 2 * 128 * 64 * 4;            // 64 KB
    cudaFuncSetAttribute(mm_half<128, false, true >, cudaFuncAttributeMaxDynamicSharedMemorySize, SM128);
    cudaFuncSetAttribute(mm_half<128, false, false>, cudaFuncAttributeMaxDynamicSharedMemorySize, SM128);
    cudaFuncSetAttribute(mm_half<128, true,  true >, cudaFuncAttributeMaxDynamicSharedMemorySize, SM128);
    cudaFuncSetAttribute(mm_half<64,  false, true >, cudaFuncAttributeMaxDynamicSharedMemorySize, SM64);
    cudaFuncSetAttribute(ktv_partial, cudaFuncAttributeMaxDynamicSharedMemorySize, SMKTV);

    dim3 tb(32, 8);
    transpose_half<<<dim3(D / 32, D / 32), tb>>>(wq, wqkvT,             D, D);
    transpose_half<<<dim3(D / 32, D / 32), tb>>>(wk, wqkvT + D * D,     D, D);
    transpose_half<<<dim3(D / 32, D / 32), tb>>>(wv, wqkvT + 2 * D * D, D, D);
    pack_bias<<<(3 * D + 255) / 256, 256>>>(bq, bk, bv, bqkv);
    ln_kernel<<<NROW, 256>>>(x, g1, be1, h1);

    // fused QKV: qkv[4096,2304] = h1 @ [wq|wk|wv] + bias   (fp16 out)
    mm_half<128, false, true><<<dim3(3 * D / 128, NROW / 128, 1), 128, SM128>>>(
        h1, D, 0, 0, wqkvT, D, 0, 0, qkv, 3 * D, 0, 0, bqkv, nullptr, 0, D, 1, 1.0f);

    // kTv = k^T @ v per head (64x64), partials + reduce
    ktv_partial<<<dim3(16, NHEAD), 256, SMKTV>>>(qkv, ktvp);
    ktv_reduce<<<NHEAD, 256>>>(ktvp, ktvT);

    // energy = q k^T / 8   (fp16 out; feeds softmax only now)
    mm_half<128, false, true><<<dim3(SEQ / 128, SEQ / 128, NHEAD), 128, SM128>>>(
        qkv,     3 * D, (size_t)SEQ * 3 * D, HD,
        qkv + D, 3 * D, (size_t)SEQ * 3 * D, HD,
        e, SEQ, (size_t)NH * SEQ * SEQ, (size_t)SEQ * SEQ,
        nullptr, nullptr, 0, HD, NH, 0.125f);

    // attention = softmax(energy)
    softmax_kernel<<<(unsigned)((size_t)NHEAD * SEQ), 256>>>(e, attn_out);

    // ctx = (1/8) q @ kTv   (associativity rewrite of energy @ v; fp16 out)
    mm_half<64, false, true><<<dim3(1, SEQ / 128, NHEAD), 128, SM64>>>(
        qkv,  3 * D, (size_t)SEQ * 3 * D, HD,
        ktvT, HD,    (size_t)NH * HD * HD, (size_t)HD * HD,
        ctx, D, (size_t)SEQ * D, HD,
        nullptr, nullptr, 0, HD, NH, 0.125f);

    // x2 = x + ctx @ wo + bo   (fp32 out)
    transpose_half<<<dim3(D / 32, D / 32), tb>>>(wo, woT, D, D);
    mm_half<128, false, false><<<dim3(D / 128, NROW / 128, 1), 128, SM128>>>(
        ctx, D, 0, 0, woT, D, 0, 0, x2, D, 0, 0, bo, x, D, D, 1, 1.0f);

    // LN2 (fp16 out)
    ln_kernel<<<NROW, 256>>>(x2, g2, be2, h2);

    // mlp = gelu(h2 @ w1 + b1)   (fp16 out)
    transpose_half<<<dim3(F / 32, D / 32), tb>>>(w1, w1T, D, F);
    mm_half<128, true, true><<<dim3(F / 128, NROW / 128, 1), 128, SM128>>>(
        h2, D, 0, 0, w1T, D, 0, 0, mlp, F, 0, 0, b1, nullptr, 0, D, 1, 1.0f);

    // out = x2 + mlp @ w2 + b2   (fp32 out)
    transpose_half<<<dim3(D / 32, F / 32), tb>>>(w2, w2T, F, D);
    mm_half<128, false, false><<<dim3(D / 128, NROW / 128, 1), 128, SM128>>>(
        mlp, F, 0, 0, w2T, F, 0, 0, out, D, 0, 0, b2, x2, D, F, 1, 1.0f);
}